// round 14
// baseline (speedup 1.0000x reference)
#include <cuda_runtime.h>
#include <cuda_bf16.h>
#include <cstdint>
#include <math.h>

#define S_LEN   2048
#define HIDDEN  4096
#define NH      32
#define NKVH    8
#define HD      128
#define QKV_DIM 6144      // (32 + 8 + 8) * 128
#define K_OFF   4096
#define V_OFF   5120

// Scratch (allocation-free rule: __device__ globals)
__device__ float g_qkv[S_LEN * QKV_DIM];            // ~50 MB
__device__ float g_attn[S_LEN * NH * HD];           // ~33 MB (tf32-rounded)
__device__ float g_hid_r[S_LEN * HIDDEN];           // tf32-rounded hidden
__device__ float g_wqkv_r[QKV_DIM * HIDDEN];        // tf32-rounded w_qkv
__device__ float g_wo_r[HIDDEN * NH * HD];          // tf32-rounded w_o
__device__ __nv_bfloat16 g_qh[NH  * S_LEN * HD];    // [h][s][d]
__device__ __nv_bfloat16 g_ql[NH  * S_LEN * HD];
__device__ __nv_bfloat16 g_kh[NKVH * S_LEN * HD];
__device__ __nv_bfloat16 g_kl[NKVH * S_LEN * HD];
__device__ __nv_bfloat16 g_vh[NKVH * S_LEN * HD];
__device__ __nv_bfloat16 g_vl[NKVH * S_LEN * HD];

__device__ __forceinline__ uint32_t smem_to_u32(const void* smem_ptr) {
    uint32_t addr;
    asm("{ .reg .u64 tmp; cvta.to.shared.u64 tmp, %1; cvt.u32.u64 %0, tmp; }"
        : "=r"(addr) : "l"(smem_ptr));
    return addr;
}

#define LDSM_X4(r0, r1, r2, r3, addr) \
    asm volatile("ldmatrix.sync.aligned.m8n8.x4.shared.b16 {%0,%1,%2,%3}, [%4];" \
                 : "=r"(r0), "=r"(r1), "=r"(r2), "=r"(r3) : "r"(addr))

#define LDSM_X4_T(r0, r1, r2, r3, addr) \
    asm volatile("ldmatrix.sync.aligned.m8n8.x4.trans.shared.b16 {%0,%1,%2,%3}, [%4];" \
                 : "=r"(r0), "=r"(r1), "=r"(r2), "=r"(r3) : "r"(addr))

__device__ __forceinline__ float round_tf32f(float x) {
    uint32_t u;
    asm("cvt.rna.tf32.f32 %0, %1;" : "=r"(u) : "f"(x));
    return __uint_as_float(u);
}

#define MMA_TF32(d, a0, a1, a2, a3, b0, b1) \
    asm volatile("mma.sync.aligned.m16n8k8.row.col.f32.tf32.tf32.f32 " \
                 "{%0,%1,%2,%3}, {%4,%5,%6,%7}, {%8,%9}, {%0,%1,%2,%3};" \
                 : "+f"((d)[0]), "+f"((d)[1]), "+f"((d)[2]), "+f"((d)[3]) \
                 : "r"(a0), "r"(a1), "r"(a2), "r"(a3), "r"(b0), "r"(b1))

#define MMA_BF16(d, a, b0, b1) \
    asm volatile("mma.sync.aligned.m16n8k16.row.col.f32.bf16.bf16.f32 " \
                 "{%0,%1,%2,%3}, {%4,%5,%6,%7}, {%8,%9}, {%0,%1,%2,%3};" \
                 : "+f"((d)[0]), "+f"((d)[1]), "+f"((d)[2]), "+f"((d)[3]) \
                 : "r"((a)[0]), "r"((a)[1]), "r"((a)[2]), "r"((a)[3]), \
                   "r"(b0), "r"(b1))

#define CP_ASYNC16(dst, src) \
    asm volatile("cp.async.cg.shared.global [%0], [%1], 16;" \
                 :: "r"(dst), "l"(src) : "memory")
#define CP_COMMIT()  asm volatile("cp.async.commit_group;" ::: "memory")
#define CP_WAIT0()   asm volatile("cp.async.wait_group 0;" ::: "memory")
#define CP_WAIT1()   asm volatile("cp.async.wait_group 1;" ::: "memory")

__device__ __forceinline__ uint32_t pack_bf16_hi(float x, float y) {
    __nv_bfloat162 t = __floats2bfloat162_rn(x, y);
    return *reinterpret_cast<uint32_t*>(&t);
}
__device__ __forceinline__ uint32_t pack_bf16_lo(float x, float y, uint32_t hi) {
    __nv_bfloat162 h = *reinterpret_cast<__nv_bfloat162*>(&hi);
    __nv_bfloat162 t = __floats2bfloat162_rn(x - __bfloat162float(h.x),
                                             y - __bfloat162float(h.y));
    return *reinterpret_cast<uint32_t*>(&t);
}

// ===========================================================================
// tf32 pre-rounding pass (rna) — keeps cvt out of the GEMM hot loop.
// ===========================================================================
__global__ void __launch_bounds__(256) round_tf32_kernel(const float* __restrict__ src,
                                                         float* __restrict__ dst,
                                                         int n4) {
    int i = blockIdx.x * blockDim.x + threadIdx.x;
    if (i >= n4) return;
    float4 v = ((const float4*)src)[i];
    v.x = round_tf32f(v.x);
    v.y = round_tf32f(v.y);
    v.z = round_tf32f(v.z);
    v.w = round_tf32f(v.w);
    ((float4*)dst)[i] = v;
}

// ===========================================================================
// tf32 mma.sync GEMM NT: C[M,N] = A[M,K] * B[N,K]^T (A, B pre-rounded tf32).
// 128x128 CTA tile, BK=32, 128 threads = 4 warps in 2x2 grid,
// 64x64 warp tile -> A and B each LDSM-read only 2x (-33% LDS per MMA),
// 32 independent MMAs per ks step (2x ILP/warp). 3-stage cp.async, single
// barrier per chunk, 2 CTAs/SM (96KB smem x2, regs <= 255).
// ===========================================================================
#define TBM 128
#define TBN 128
#define TBK 32
#define TILE_BYTES (TBM * TBK * 4)       // 16384
#define STAGE_BYTES (2 * TILE_BYTES)     // A+B per stage = 32768
#define NSTAGE 3
#define GEMM_SMEM_TOTAL (NSTAGE * STAGE_BYTES)   // 98304

__global__ void __launch_bounds__(128) tmma_gemm_nt(const float* __restrict__ A,
                                                    const float* __restrict__ B,
                                                    float* __restrict__ C,
                                                    int N, int K) {
    extern __shared__ char smem[];
    const uint32_t sbase = smem_to_u32(smem);
    const int tid = threadIdx.x;
    const int lane = tid & 31;
    const int wid = tid >> 5;
    const int warp_m = wid & 1;        // 2 x 64 rows
    const int warp_n = wid >> 1;       // 2 x 64 cols
    const int row0 = blockIdx.x * TBM;
    const int col0 = blockIdx.y * TBN;

    const int seg = lane >> 3, r8 = lane & 7;
    const int a_row_off = ((seg & 1) << 3) + r8;
    const int a_kh = seg >> 1;
    const int b_row_off = ((seg >> 1) << 3) + r8;
    const int b_kh = seg & 1;

    float acc[4][8][4] = {};           // [mf][nf][c] = 128 floats
    const int NCHUNK = K / TBK;

    const int lrr = tid >> 3, lcj = tid & 7;   // 128 thr cover 16 rows x 8 grp

    auto load_chunk = [&](int c, int st) {
        const uint32_t sA = sbase + (uint32_t)st * STAGE_BYTES;
        const uint32_t sB = sA + TILE_BYTES;
        const int k0 = c * TBK;
        #pragma unroll
        for (int i = 0; i < 8; i++) {
            int rr = lrr + i * 16;
            uint32_t so = (uint32_t)rr * 128u + (uint32_t)((lcj ^ (rr & 7)) << 4);
            const float* gA = A + (size_t)(row0 + rr) * K + k0 + lcj * 4;
            const float* gB = B + (size_t)(col0 + rr) * K + k0 + lcj * 4;
            CP_ASYNC16(sA + so, gA);
            CP_ASYNC16(sB + so, gB);
        }
        CP_COMMIT();
    };

    load_chunk(0, 0);
    load_chunk(1, 1);

    int st = 0;
    for (int c = 0; c < NCHUNK; c++) {
        if (c < NCHUNK - 1) CP_WAIT1(); else CP_WAIT0();
        __syncthreads();                 // single barrier per chunk (R12-proven)
        if (c + 2 < NCHUNK) {
            int st2 = st + 2; if (st2 >= NSTAGE) st2 -= NSTAGE;
            load_chunk(c + 2, st2);
        }

        const uint32_t sA = sbase + (uint32_t)st * STAGE_BYTES;
        const uint32_t sB = sA + TILE_BYTES;
        #pragma unroll
        for (int ks = 0; ks < 4; ks++) {
            uint32_t a[4][4], b[4][4];
            #pragma unroll
            for (int mf = 0; mf < 4; mf++) {
                int row = warp_m * 64 + mf * 16 + a_row_off;
                uint32_t g = (uint32_t)((ks * 2 + a_kh) ^ (row & 7));
                uint32_t addr = sA + (uint32_t)row * 128u + g * 16u;
                LDSM_X4(a[mf][0], a[mf][1], a[mf][2], a[mf][3], addr);
            }
            #pragma unroll
            for (int nf2 = 0; nf2 < 4; nf2++) {
                int row = warp_n * 64 + nf2 * 16 + b_row_off;
                uint32_t g = (uint32_t)((ks * 2 + b_kh) ^ (row & 7));
                uint32_t addr = sB + (uint32_t)row * 128u + g * 16u;
                LDSM_X4(b[nf2][0], b[nf2][1], b[nf2][2], b[nf2][3], addr);
            }
            #pragma unroll
            for (int mf = 0; mf < 4; mf++)
                #pragma unroll
                for (int nf = 0; nf < 8; nf++) {
                    uint32_t bb0 = b[nf >> 1][(nf & 1) * 2 + 0];
                    uint32_t bb1 = b[nf >> 1][(nf & 1) * 2 + 1];
                    MMA_TF32(acc[mf][nf], a[mf][0], a[mf][1], a[mf][2], a[mf][3],
                             bb0, bb1);
                }
        }
        if (++st >= NSTAGE) st = 0;
    }

    #pragma unroll
    for (int mf = 0; mf < 4; mf++) {
        int grow = row0 + warp_m * 64 + mf * 16 + (lane >> 2);
        #pragma unroll
        for (int nf = 0; nf < 8; nf++) {
            int gcol = col0 + warp_n * 64 + nf * 8 + ((lane & 3) << 1);
            *(float2*)(C + (size_t)grow * N + gcol) =
                make_float2(acc[mf][nf][0], acc[mf][nf][1]);
            *(float2*)(C + (size_t)(grow + 8) * N + gcol) =
                make_float2(acc[mf][nf][2], acc[mf][nf][3]);
        }
    }
}

// ===========================================================================
// RoPE + bf16 hi/lo split pre-pass (unchanged).
// ===========================================================================
__global__ void rope_split_kernel() {
    int idx = blockIdx.x * blockDim.x + threadIdx.x;
    if (idx >= S_LEN * 48 * 64) return;
    int d = idx & 63;
    int h = (idx >> 6) % 48;
    int s = idx / (64 * 48);

    float x1, x2;
    __nv_bfloat16 *dst_h, *dst_l;
    if (h < 32) {
        const float* src = g_qkv + (size_t)s * QKV_DIM + h * HD;
        x1 = src[d]; x2 = src[d + 64];
        dst_h = g_qh + ((size_t)h * S_LEN + s) * HD;
        dst_l = g_ql + ((size_t)h * S_LEN + s) * HD;
    } else if (h < 40) {
        const float* src = g_qkv + (size_t)s * QKV_DIM + K_OFF + (h - 32) * HD;
        x1 = src[d]; x2 = src[d + 64];
        dst_h = g_kh + ((size_t)(h - 32) * S_LEN + s) * HD;
        dst_l = g_kl + ((size_t)(h - 32) * S_LEN + s) * HD;
    } else {
        const float* src = g_qkv + (size_t)s * QKV_DIM + V_OFF + (h - 40) * HD;
        x1 = src[d]; x2 = src[d + 64];
        dst_h = g_vh + ((size_t)(h - 40) * S_LEN + s) * HD;
        dst_l = g_vl + ((size_t)(h - 40) * S_LEN + s) * HD;
    }

    float o1 = x1, o2 = x2;
    if (h < 40) {
        float freq = exp2f(-0.20762050593046013f * (float)d);
        float ang = (float)s * freq;
        float sn, cs;
        sincosf(ang, &sn, &cs);
        o1 = x1 * cs - x2 * sn;
        o2 = x1 * sn + x2 * cs;
    }
    if (h < 32) {
        const float scale = 0.08838834764831845f;   // 1/sqrt(128)
        o1 *= scale; o2 *= scale;
    }
    __nv_bfloat16 h1 = __float2bfloat16_rn(o1);
    __nv_bfloat16 h2 = __float2bfloat16_rn(o2);
    dst_h[d]      = h1;
    dst_h[d + 64] = h2;
    dst_l[d]      = __float2bfloat16_rn(o1 - __bfloat162float(h1));
    dst_l[d + 64] = __float2bfloat16_rn(o2 - __bfloat162float(h2));
}

// ===========================================================================
// Tensor-core flash attention, bf16 3-term compensated — R8/R12's proven
// 64-row version (2 CTAs/SM, V-wait hidden behind QK+softmax, K-wait
// behind PV). Unchanged.
// ===========================================================================
#define ATT_SMEM (6 * 64 * 128 * 2)    // 98304 bytes
#define SQH 0
#define SQL 16384
#define SKH 32768
#define SKL 49152
#define SVH 65536
#define SVL 81920

__global__ void __launch_bounds__(128, 2) attn_mma() {
    extern __shared__ char smem[];
    const uint32_t sb = smem_to_u32(smem);
    const int tid = threadIdx.x;
    const int lane = tid & 31;
    const int wid = tid >> 5;
    const int mb = 31 - (int)blockIdx.x;     // heaviest first
    const int h = blockIdx.y;
    const int kvh = h >> 2;
    const int q0 = mb * 64;
    const int wr = wid * 16;
    const int gr = lane >> 2, tg = lane & 3;
    const int seg = lane >> 3, r8 = lane & 7;

    const __nv_bfloat16* qh = g_qh + ((size_t)h * S_LEN + q0) * HD;
    const __nv_bfloat16* ql = g_ql + ((size_t)h * S_LEN + q0) * HD;
    const __nv_bfloat16* kh = g_kh + (size_t)kvh * S_LEN * HD;
    const __nv_bfloat16* kl = g_kl + (size_t)kvh * S_LEN * HD;
    const __nv_bfloat16* vh = g_vh + (size_t)kvh * S_LEN * HD;
    const __nv_bfloat16* vl = g_vl + (size_t)kvh * S_LEN * HD;

    auto load_pair = [&](uint32_t dh, uint32_t dl,
                         const __nv_bfloat16* sh, const __nv_bfloat16* sl) {
        #pragma unroll
        for (int i = 0; i < 8; i++) {
            int e = tid + i * 128;
            int r = e >> 4, g = e & 15;
            uint32_t so = (uint32_t)r * 256u + (uint32_t)((g ^ (r & 7)) << 4);
            CP_ASYNC16(dh + so, sh + (size_t)r * HD + g * 8);
            CP_ASYNC16(dl + so, sl + (size_t)r * HD + g * 8);
        }
    };

    load_pair(sb + SQH, sb + SQL, qh, ql);
    load_pair(sb + SKH, sb + SKL, kh, kl);
    load_pair(sb + SVH, sb + SVL, vh, vl);
    CP_COMMIT();
    CP_WAIT0();
    __syncthreads();

    float oacc[16][4] = {};
    const float NEG_INF = -__int_as_float(0x7f800000);
    float m0 = NEG_INF, m1 = NEG_INF, l0 = 0.0f, l1 = 0.0f;

    const int a_row = wr + ((seg & 1) << 3) + r8;
    const int a_gsel = seg >> 1;
    const int b_row_off = ((seg >> 1) << 3) + r8;
    const int b_gsel = seg & 1;
    const int v_row_off = ((seg & 1) << 3) + r8;
    const int v_gsel = seg >> 1;

    for (int kb = 0; kb <= mb; kb++) {
        // ---------------- S = Q K^T (bf16 x3) ----------------
        float sacc[8][4] = {};
        #pragma unroll
        for (int kc = 0; kc < 8; kc++) {
            uint32_t qa_h[4], qa_l[4];
            {
                uint32_t g = (uint32_t)((2 * kc + a_gsel) ^ (a_row & 7));
                uint32_t off = (uint32_t)a_row * 256u + g * 16u;
                LDSM_X4(qa_h[0], qa_h[1], qa_h[2], qa_h[3], sb + SQH + off);
                LDSM_X4(qa_l[0], qa_l[1], qa_l[2], qa_l[3], sb + SQL + off);
            }
            #pragma unroll
            for (int nf2 = 0; nf2 < 4; nf2++) {
                int brow = nf2 * 16 + b_row_off;
                uint32_t g = (uint32_t)((2 * kc + b_gsel) ^ (brow & 7));
                uint32_t off = (uint32_t)brow * 256u + g * 16u;
                uint32_t bh0, bh1, bh2, bh3, bl0, bl1, bl2, bl3;
                LDSM_X4(bh0, bh1, bh2, bh3, sb + SKH + off);
                LDSM_X4(bl0, bl1, bl2, bl3, sb + SKL + off);
                MMA_BF16(sacc[2 * nf2],     qa_h, bh0, bh1);
                MMA_BF16(sacc[2 * nf2],     qa_l, bh0, bh1);
                MMA_BF16(sacc[2 * nf2],     qa_h, bl0, bl1);
                MMA_BF16(sacc[2 * nf2 + 1], qa_h, bh2, bh3);
                MMA_BF16(sacc[2 * nf2 + 1], qa_l, bh2, bh3);
                MMA_BF16(sacc[2 * nf2 + 1], qa_h, bl2, bl3);
            }
        }
        __syncthreads();                      // K tile consumed
        if (kb < mb) {                        // prefetch next K
            load_pair(sb + SKH, sb + SKL,
                      kh + (size_t)(kb + 1) * 64 * HD,
                      kl + (size_t)(kb + 1) * 64 * HD);
            CP_COMMIT();
        }

        // ---------------- online softmax (registers only) ----------------
        const int row0g = q0 + wr + gr;
        const int row1g = row0g + 8;
        if (kb == mb) {
            const int n0 = kb * 64;
            #pragma unroll
            for (int nf = 0; nf < 8; nf++) {
                int c0 = n0 + nf * 8 + 2 * tg;
                if (c0 > row0g)     sacc[nf][0] = NEG_INF;
                if (c0 + 1 > row0g) sacc[nf][1] = NEG_INF;
                if (c0 > row1g)     sacc[nf][2] = NEG_INF;
                if (c0 + 1 > row1g) sacc[nf][3] = NEG_INF;
            }
        }
        float mx0 = NEG_INF, mx1 = NEG_INF;
        #pragma unroll
        for (int nf = 0; nf < 8; nf++) {
            mx0 = fmaxf(mx0, fmaxf(sacc[nf][0], sacc[nf][1]));
            mx1 = fmaxf(mx1, fmaxf(sacc[nf][2], sacc[nf][3]));
        }
        mx0 = fmaxf(mx0, __shfl_xor_sync(0xffffffffu, mx0, 1));
        mx0 = fmaxf(mx0, __shfl_xor_sync(0xffffffffu, mx0, 2));
        mx1 = fmaxf(mx1, __shfl_xor_sync(0xffffffffu, mx1, 1));
        mx1 = fmaxf(mx1, __shfl_xor_sync(0xffffffffu, mx1, 2));
        float mn0 = fmaxf(m0, mx0), mn1 = fmaxf(m1, mx1);
        float rs0 = __expf(m0 - mn0), rs1 = __expf(m1 - mn1);
        float sum0 = 0.0f, sum1 = 0.0f;
        #pragma unroll
        for (int nf = 0; nf < 8; nf++) {
            sacc[nf][0] = __expf(sacc[nf][0] - mn0); sum0 += sacc[nf][0];
            sacc[nf][1] = __expf(sacc[nf][1] - mn0); sum0 += sacc[nf][1];
            sacc[nf][2] = __expf(sacc[nf][2] - mn1); sum1 += sacc[nf][2];
            sacc[nf][3] = __expf(sacc[nf][3] - mn1); sum1 += sacc[nf][3];
        }
        sum0 += __shfl_xor_sync(0xffffffffu, sum0, 1);
        sum0 += __shfl_xor_sync(0xffffffffu, sum0, 2);
        sum1 += __shfl_xor_sync(0xffffffffu, sum1, 1);
        sum1 += __shfl_xor_sync(0xffffffffu, sum1, 2);
        l0 = l0 * rs0 + sum0; m0 = mn0;
        l1 = l1 * rs1 + sum1; m1 = mn1;
        #pragma unroll
        for (int nf = 0; nf < 16; nf++) {
            oacc[nf][0] *= rs0; oacc[nf][1] *= rs0;
            oacc[nf][2] *= rs1; oacc[nf][3] *= rs1;
        }

        // V_kb resident check (load issued last iteration, hidden by QK+softmax)
        if (kb > 0) {
            if (kb < mb) CP_WAIT1(); else CP_WAIT0();
            __syncthreads();
        }

        // ---------------- O += P V (bf16 x3, P from regs) ----------------
        #pragma unroll
        for (int kc2 = 0; kc2 < 4; kc2++) {
            uint32_t pa_h[4], pa_l[4];
            pa_h[0] = pack_bf16_hi(sacc[2 * kc2][0],     sacc[2 * kc2][1]);
            pa_h[1] = pack_bf16_hi(sacc[2 * kc2][2],     sacc[2 * kc2][3]);
            pa_h[2] = pack_bf16_hi(sacc[2 * kc2 + 1][0], sacc[2 * kc2 + 1][1]);
            pa_h[3] = pack_bf16_hi(sacc[2 * kc2 + 1][2], sacc[2 * kc2 + 1][3]);
            pa_l[0] = pack_bf16_lo(sacc[2 * kc2][0],     sacc[2 * kc2][1],     pa_h[0]);
            pa_l[1] = pack_bf16_lo(sacc[2 * kc2][2],     sacc[2 * kc2][3],     pa_h[1]);
            pa_l[2] = pack_bf16_lo(sacc[2 * kc2 + 1][0], sacc[2 * kc2 + 1][1], pa_h[2]);
            pa_l[3] = pack_bf16_lo(sacc[2 * kc2 + 1][2], sacc[2 * kc2 + 1][3], pa_h[3]);
            int krow = 16 * kc2 + v_row_off;
            #pragma unroll
            for (int j = 0; j < 8; j++) {
                uint32_t g = (uint32_t)((2 * j + v_gsel) ^ (krow & 7));
                uint32_t off = (uint32_t)krow * 256u + g * 16u;
                uint32_t vh0, vh1, vh2, vh3, vl0, vl1, vl2, vl3;
                LDSM_X4_T(vh0, vh1, vh2, vh3, sb + SVH + off);
                LDSM_X4_T(vl0, vl1, vl2, vl3, sb + SVL + off);
                MMA_BF16(oacc[2 * j],     pa_h, vh0, vh1);
                MMA_BF16(oacc[2 * j],     pa_l, vh0, vh1);
                MMA_BF16(oacc[2 * j],     pa_h, vl0, vl1);
                MMA_BF16(oacc[2 * j + 1], pa_h, vh2, vh3);
                MMA_BF16(oacc[2 * j + 1], pa_l, vh2, vh3);
                MMA_BF16(oacc[2 * j + 1], pa_h, vl2, vl3);
            }
        }
        __syncthreads();                      // V tile consumed
        if (kb < mb) {
            load_pair(sb + SVH, sb + SVL,
                      vh + (size_t)(kb + 1) * 64 * HD,
                      vl + (size_t)(kb + 1) * 64 * HD);
            CP_COMMIT();
            CP_WAIT1();                       // K_{kb+1} done
            __syncthreads();
        }
    }

    // ---------------- normalize + tf32-round + writeout ----------------
    const float inv0 = 1.0f / l0, inv1 = 1.0f / l1;
    const int row0g = q0 + wr + gr;
    float* dst0 = g_attn + (size_t)row0g * (NH * HD) + h * HD;
    float* dst1 = dst0 + 8 * (size_t)(NH * HD);
    #pragma unroll
    for (int nf = 0; nf < 16; nf++) {
        int col = nf * 8 + 2 * tg;
        *(float2*)(dst0 + col) = make_float2(round_tf32f(oacc[nf][0] * inv0),
                                             round_tf32f(oacc[nf][1] * inv0));
        *(float2*)(dst1 + col) = make_float2(round_tf32f(oacc[nf][2] * inv1),
                                             round_tf32f(oacc[nf][3] * inv1));
    }
}

// ---------------------------------------------------------------------------
extern "C" void kernel_launch(void* const* d_in, const int* in_sizes, int n_in,
                              void* d_out, int out_size) {
    const float* hidden = (const float*)d_in[0];
    const float* w_qkv  = (const float*)d_in[1];
    const float* w_o    = (const float*)d_in[2];
    float* out = (float*)d_out;

    float *qkv = nullptr, *attn = nullptr;
    float *hid_r = nullptr, *wqkv_r = nullptr, *wo_r = nullptr;
    cudaGetSymbolAddress((void**)&qkv,    g_qkv);
    cudaGetSymbolAddress((void**)&attn,   g_attn);
    cudaGetSymbolAddress((void**)&hid_r,  g_hid_r);
    cudaGetSymbolAddress((void**)&wqkv_r, g_wqkv_r);
    cudaGetSymbolAddress((void**)&wo_r,   g_wo_r);

    cudaFuncSetAttribute(tmma_gemm_nt, cudaFuncAttributeMaxDynamicSharedMemorySize,
                         GEMM_SMEM_TOTAL);
    cudaFuncSetAttribute(attn_mma, cudaFuncAttributeMaxDynamicSharedMemorySize,
                         ATT_SMEM);

    // 0) tf32 pre-rounding of GEMM operands
    {
        int n4;
        n4 = (QKV_DIM * HIDDEN) / 4;
        round_tf32_kernel<<<(n4 + 255) / 256, 256>>>(w_qkv, wqkv_r, n4);
        n4 = (HIDDEN * NH * HD) / 4;
        round_tf32_kernel<<<(n4 + 255) / 256, 256>>>(w_o, wo_r, n4);
        n4 = (S_LEN * HIDDEN) / 4;
        round_tf32_kernel<<<(n4 + 255) / 256, 256>>>(hidden, hid_r, n4);
    }

    // 1) QKV projection (tf32 mma): [2048,6144] = hidden @ w_qkv^T
    tmma_gemm_nt<<<dim3(S_LEN / TBM, QKV_DIM / TBN), 128, GEMM_SMEM_TOTAL>>>(
        hid_r, wqkv_r, qkv, QKV_DIM, HIDDEN);

    // 2) RoPE + scale + bf16 hi/lo split -> head-major Q/K/V
    rope_split_kernel<<<(S_LEN * 48 * 64 + 255) / 256, 256>>>();

    // 3) Causal GQA flash attention (bf16 x3 tensor core) -> g_attn (tf32-rounded)
    attn_mma<<<dim3(32, NH), 128, ATT_SMEM>>>();

    // 4) Output projection (tf32 mma): out = g_attn @ w_o^T
    tmma_gemm_nt<<<dim3(S_LEN / TBM, HIDDEN / TBN), 128, GEMM_SMEM_TOTAL>>>(
        attn, wo_r, out, HIDDEN, HIDDEN);
}

// round 15
// speedup vs baseline: 1.0916x; 1.0916x over previous
#include <cuda_runtime.h>
#include <cuda_bf16.h>
#include <cstdint>
#include <math.h>

#define S_LEN   2048
#define HIDDEN  4096
#define NH      32
#define NKVH    8
#define HD      128
#define QKV_DIM 6144      // (32 + 8 + 8) * 128

// Scratch (allocation-free rule: __device__ globals)
__device__ float g_attn[S_LEN * NH * HD];           // tf32-rounded attention out
__device__ float g_hid_r[S_LEN * HIDDEN];           // tf32-rounded hidden
__device__ float g_wqkv_r[QKV_DIM * HIDDEN];        // tf32-rounded w_qkv
__device__ float g_wo_r[HIDDEN * NH * HD];          // tf32-rounded w_o
__device__ __nv_bfloat16 g_qh[NH  * S_LEN * HD];    // [h][s][d]
__device__ __nv_bfloat16 g_ql[NH  * S_LEN * HD];
__device__ __nv_bfloat16 g_kh[NKVH * S_LEN * HD];
__device__ __nv_bfloat16 g_kl[NKVH * S_LEN * HD];
__device__ __nv_bfloat16 g_vh[NKVH * S_LEN * HD];
__device__ __nv_bfloat16 g_vl[NKVH * S_LEN * HD];

__device__ __forceinline__ uint32_t smem_to_u32(const void* smem_ptr) {
    uint32_t addr;
    asm("{ .reg .u64 tmp; cvta.to.shared.u64 tmp, %1; cvt.u32.u64 %0, tmp; }"
        : "=r"(addr) : "l"(smem_ptr));
    return addr;
}

#define LDSM_X4(r0, r1, r2, r3, addr) \
    asm volatile("ldmatrix.sync.aligned.m8n8.x4.shared.b16 {%0,%1,%2,%3}, [%4];" \
                 : "=r"(r0), "=r"(r1), "=r"(r2), "=r"(r3) : "r"(addr))

#define LDSM_X4_T(r0, r1, r2, r3, addr) \
    asm volatile("ldmatrix.sync.aligned.m8n8.x4.trans.shared.b16 {%0,%1,%2,%3}, [%4];" \
                 : "=r"(r0), "=r"(r1), "=r"(r2), "=r"(r3) : "r"(addr))

__device__ __forceinline__ float round_tf32f(float x) {
    uint32_t u;
    asm("cvt.rna.tf32.f32 %0, %1;" : "=r"(u) : "f"(x));
    return __uint_as_float(u);
}

#define MMA_TF32(d, a0, a1, a2, a3, b0, b1) \
    asm volatile("mma.sync.aligned.m16n8k8.row.col.f32.tf32.tf32.f32 " \
                 "{%0,%1,%2,%3}, {%4,%5,%6,%7}, {%8,%9}, {%0,%1,%2,%3};" \
                 : "+f"((d)[0]), "+f"((d)[1]), "+f"((d)[2]), "+f"((d)[3]) \
                 : "r"(a0), "r"(a1), "r"(a2), "r"(a3), "r"(b0), "r"(b1))

#define MMA_BF16(d, a, b0, b1) \
    asm volatile("mma.sync.aligned.m16n8k16.row.col.f32.bf16.bf16.f32 " \
                 "{%0,%1,%2,%3}, {%4,%5,%6,%7}, {%8,%9}, {%0,%1,%2,%3};" \
                 : "+f"((d)[0]), "+f"((d)[1]), "+f"((d)[2]), "+f"((d)[3]) \
                 : "r"((a)[0]), "r"((a)[1]), "r"((a)[2]), "r"((a)[3]), \
                   "r"(b0), "r"(b1))

#define CP_ASYNC16(dst, src) \
    asm volatile("cp.async.cg.shared.global [%0], [%1], 16;" \
                 :: "r"(dst), "l"(src) : "memory")
#define CP_COMMIT()  asm volatile("cp.async.commit_group;" ::: "memory")
#define CP_WAIT0()   asm volatile("cp.async.wait_group 0;" ::: "memory")
#define CP_WAIT1()   asm volatile("cp.async.wait_group 1;" ::: "memory")

__device__ __forceinline__ uint32_t pack_bf16_hi(float x, float y) {
    __nv_bfloat162 t = __floats2bfloat162_rn(x, y);
    return *reinterpret_cast<uint32_t*>(&t);
}
__device__ __forceinline__ uint32_t pack_bf16_lo(float x, float y, uint32_t hi) {
    __nv_bfloat162 h = *reinterpret_cast<__nv_bfloat162*>(&hi);
    __nv_bfloat162 t = __floats2bfloat162_rn(x - __bfloat162float(h.x),
                                             y - __bfloat162float(h.y));
    return *reinterpret_cast<uint32_t*>(&t);
}

// ===========================================================================
// tf32 pre-rounding pass (rna) — keeps cvt out of the GEMM hot loop.
// ===========================================================================
__global__ void __launch_bounds__(256) round_tf32_kernel(const float* __restrict__ src,
                                                         float* __restrict__ dst,
                                                         int n4) {
    int i = blockIdx.x * blockDim.x + threadIdx.x;
    if (i >= n4) return;
    float4 v = ((const float4*)src)[i];
    v.x = round_tf32f(v.x);
    v.y = round_tf32f(v.y);
    v.z = round_tf32f(v.z);
    v.w = round_tf32f(v.w);
    ((float4*)dst)[i] = v;
}

// ===========================================================================
// Shared GEMM mainloop config — R12-proven optimum:
// 128x128 CTA tile, BK=32, 256 threads, 8 warps 2(M)x4(N), 64x32 warp tile,
// 3-stage cp.async, single barrier per chunk, 2 CTAs/SM.
// ===========================================================================
#define TBM 128
#define TBN 128
#define TBK 32
#define TILE_BYTES (TBM * TBK * 4)       // 16384
#define STAGE_BYTES (2 * TILE_BYTES)     // A+B per stage = 32768
#define NSTAGE 3
#define GEMM_SMEM_TOTAL (NSTAGE * STAGE_BYTES)   // 98304
#define EP_STRIDE 132                    // epilogue staging row stride (floats)

// Mainloop as a macro-like inline: computes acc[4][4][4] for this CTA tile.
#define GEMM_MAINLOOP(A_PTR, B_PTR, KDIM)                                      \
    const int lrr = tid >> 3, lcj = tid & 7;                                   \
    auto load_chunk = [&](int c, int stg) {                                    \
        const uint32_t sA = sbase + (uint32_t)stg * STAGE_BYTES;               \
        const uint32_t sB = sA + TILE_BYTES;                                   \
        const int k0 = c * TBK;                                                \
        _Pragma("unroll")                                                      \
        for (int i = 0; i < 4; i++) {                                          \
            int rr = lrr + i * 32;                                             \
            uint32_t so = (uint32_t)rr * 128u + (uint32_t)((lcj ^ (rr & 7)) << 4); \
            const float* gA = (A_PTR) + (size_t)(row0 + rr) * (KDIM) + k0 + lcj * 4; \
            const float* gB = (B_PTR) + (size_t)(col0 + rr) * (KDIM) + k0 + lcj * 4; \
            CP_ASYNC16(sA + so, gA);                                           \
            CP_ASYNC16(sB + so, gB);                                           \
        }                                                                      \
        CP_COMMIT();                                                           \
    };                                                                         \
    load_chunk(0, 0);                                                          \
    load_chunk(1, 1);                                                          \
    int st = 0;                                                                \
    const int NCHUNK = (KDIM) / TBK;                                           \
    for (int c = 0; c < NCHUNK; c++) {                                         \
        if (c < NCHUNK - 1) CP_WAIT1(); else CP_WAIT0();                       \
        __syncthreads();                                                       \
        if (c + 2 < NCHUNK) {                                                  \
            int st2 = st + 2; if (st2 >= NSTAGE) st2 -= NSTAGE;                \
            load_chunk(c + 2, st2);                                            \
        }                                                                      \
        const uint32_t sA = sbase + (uint32_t)st * STAGE_BYTES;                \
        const uint32_t sB = sA + TILE_BYTES;                                   \
        _Pragma("unroll")                                                      \
        for (int ks = 0; ks < 4; ks++) {                                       \
            uint32_t a[4][4], b[2][4];                                         \
            _Pragma("unroll")                                                  \
            for (int mf = 0; mf < 4; mf++) {                                   \
                int row = warp_m * 64 + mf * 16 + a_row_off;                   \
                uint32_t g = (uint32_t)((ks * 2 + a_kh) ^ (row & 7));          \
                uint32_t addr = sA + (uint32_t)row * 128u + g * 16u;           \
                LDSM_X4(a[mf][0], a[mf][1], a[mf][2], a[mf][3], addr);         \
            }                                                                  \
            _Pragma("unroll")                                                  \
            for (int nf2 = 0; nf2 < 2; nf2++) {                                \
                int row = warp_n * 32 + nf2 * 16 + b_row_off;                  \
                uint32_t g = (uint32_t)((ks * 2 + b_kh) ^ (row & 7));          \
                uint32_t addr = sB + (uint32_t)row * 128u + g * 16u;           \
                LDSM_X4(b[nf2][0], b[nf2][1], b[nf2][2], b[nf2][3], addr);     \
            }                                                                  \
            _Pragma("unroll")                                                  \
            for (int mf = 0; mf < 4; mf++)                                     \
                _Pragma("unroll")                                              \
                for (int nf = 0; nf < 4; nf++) {                               \
                    uint32_t bb0 = b[nf >> 1][(nf & 1) * 2 + 0];               \
                    uint32_t bb1 = b[nf >> 1][(nf & 1) * 2 + 1];               \
                    MMA_TF32(acc[mf][nf], a[mf][0], a[mf][1], a[mf][2],        \
                             a[mf][3], bb0, bb1);                              \
                }                                                              \
        }                                                                      \
        if (++st >= NSTAGE) st = 0;                                            \
    }

// ---------------------------------------------------------------------------
// Generic GEMM NT (used for O projection): C = A * B^T
// ---------------------------------------------------------------------------
__global__ void __launch_bounds__(256) tmma_gemm_nt(const float* __restrict__ A,
                                                    const float* __restrict__ B,
                                                    float* __restrict__ C,
                                                    int N, int K) {
    extern __shared__ char smem[];
    const uint32_t sbase = smem_to_u32(smem);
    const int tid = threadIdx.x;
    const int lane = tid & 31;
    const int wid = tid >> 5;
    const int warp_m = wid & 1;
    const int warp_n = wid >> 1;
    const int row0 = blockIdx.x * TBM;
    const int col0 = blockIdx.y * TBN;

    const int seg = lane >> 3, r8 = lane & 7;
    const int a_row_off = ((seg & 1) << 3) + r8;
    const int a_kh = seg >> 1;
    const int b_row_off = ((seg >> 1) << 3) + r8;
    const int b_kh = seg & 1;

    float acc[4][4][4] = {};

    GEMM_MAINLOOP(A, B, K)

    #pragma unroll
    for (int mf = 0; mf < 4; mf++) {
        int grow = row0 + warp_m * 64 + mf * 16 + (lane >> 2);
        #pragma unroll
        for (int nf = 0; nf < 4; nf++) {
            int gcol = col0 + warp_n * 32 + nf * 8 + ((lane & 3) << 1);
            *(float2*)(C + (size_t)grow * N + gcol) =
                make_float2(acc[mf][nf][0], acc[mf][nf][1]);
            *(float2*)(C + (size_t)(grow + 8) * N + gcol) =
                make_float2(acc[mf][nf][2], acc[mf][nf][3]);
        }
    }
}

// ---------------------------------------------------------------------------
// QKV GEMM with FUSED RoPE + scale + bf16 hi/lo split epilogue.
// N-tile (128 cols) == one head; blockIdx.y = head region hh in [0,48):
//   hh<32 : Q head (RoPE + 1/sqrt(HD))   -> g_qh/g_ql [hh][s][d]
//   hh<40 : K head (RoPE)               -> g_kh/g_kl [hh-32][s][d]
//   else  : V head (copy)               -> g_vh/g_vl [hh-40][s][d]
// Accumulator tile staged fp32 in pipeline smem; rope pairs (d, d+64)
// cross warps, resolved via the staging tile. Math identical to the old
// rope_split_kernel -> outputs unchanged.
// ---------------------------------------------------------------------------
__global__ void __launch_bounds__(256) tmma_gemm_qkv_fused(const float* __restrict__ A,
                                                           const float* __restrict__ B) {
    extern __shared__ char smem[];
    const uint32_t sbase = smem_to_u32(smem);
    const int tid = threadIdx.x;
    const int lane = tid & 31;
    const int wid = tid >> 5;
    const int warp_m = wid & 1;
    const int warp_n = wid >> 1;
    const int row0 = blockIdx.x * TBM;
    const int col0 = blockIdx.y * TBN;
    const int hh = blockIdx.y;           // head region (tile = one head)

    const int seg = lane >> 3, r8 = lane & 7;
    const int a_row_off = ((seg & 1) << 3) + r8;
    const int a_kh = seg >> 1;
    const int b_row_off = ((seg >> 1) << 3) + r8;
    const int b_kh = seg & 1;

    float acc[4][4][4] = {};

    GEMM_MAINLOOP(A, B, HIDDEN)

    // ---- epilogue: stage acc tile in smem (pipeline buffers are free) ----
    __syncthreads();                      // all MMAs done, smem reusable
    float* T = (float*)smem;              // [128][EP_STRIDE]
    #pragma unroll
    for (int mf = 0; mf < 4; mf++) {
        int r = warp_m * 64 + mf * 16 + (lane >> 2);
        #pragma unroll
        for (int nf = 0; nf < 4; nf++) {
            int cc = warp_n * 32 + nf * 8 + ((lane & 3) << 1);
            *(float2*)(T + r * EP_STRIDE + cc) =
                make_float2(acc[mf][nf][0], acc[mf][nf][1]);
            *(float2*)(T + (r + 8) * EP_STRIDE + cc) =
                make_float2(acc[mf][nf][2], acc[mf][nf][3]);
        }
    }
    __syncthreads();

    // ---- rope + scale + bf16 split, 8192 (row, d-pair) items / 256 thr ----
    __nv_bfloat16 *base_h, *base_l;
    int head;
    if (hh < 32)      { base_h = g_qh; base_l = g_ql; head = hh; }
    else if (hh < 40) { base_h = g_kh; base_l = g_kl; head = hh - 32; }
    else              { base_h = g_vh; base_l = g_vl; head = hh - 40; }
    const bool do_rope  = (hh < 40);
    const bool do_scale = (hh < 32);

    #pragma unroll 4
    for (int i = 0; i < 32; i++) {
        int e = tid + i * 256;            // 0..8191
        int r = e >> 6;                   // 0..127
        int d = e & 63;                   // 0..63
        float x1 = T[r * EP_STRIDE + d];
        float x2 = T[r * EP_STRIDE + d + 64];
        int s = row0 + r;

        float o1 = x1, o2 = x2;
        if (do_rope) {
            float freq = exp2f(-0.20762050593046013f * (float)d);
            float ang = (float)s * freq;
            float sn, cs;
            sincosf(ang, &sn, &cs);
            o1 = x1 * cs - x2 * sn;
            o2 = x1 * sn + x2 * cs;
        }
        if (do_scale) {
            const float scale = 0.08838834764831845f;   // 1/sqrt(128)
            o1 *= scale; o2 *= scale;
        }
        __nv_bfloat16 h1 = __float2bfloat16_rn(o1);
        __nv_bfloat16 h2 = __float2bfloat16_rn(o2);
        size_t off = ((size_t)head * S_LEN + s) * HD + d;
        base_h[off]      = h1;
        base_h[off + 64] = h2;
        base_l[off]      = __float2bfloat16_rn(o1 - __bfloat162float(h1));
        base_l[off + 64] = __float2bfloat16_rn(o2 - __bfloat162float(h2));
    }
}

// ===========================================================================
// Tensor-core flash attention, bf16 3-term compensated — R8/R12's proven
// 64-row version (2 CTAs/SM, V-wait hidden behind QK+softmax, K-wait
// behind PV). Unchanged.
// ===========================================================================
#define ATT_SMEM (6 * 64 * 128 * 2)    // 98304 bytes
#define SQH 0
#define SQL 16384
#define SKH 32768
#define SKL 49152
#define SVH 65536
#define SVL 81920

__global__ void __launch_bounds__(128, 2) attn_mma() {
    extern __shared__ char smem[];
    const uint32_t sb = smem_to_u32(smem);
    const int tid = threadIdx.x;
    const int lane = tid & 31;
    const int wid = tid >> 5;
    const int mb = 31 - (int)blockIdx.x;     // heaviest first
    const int h = blockIdx.y;
    const int kvh = h >> 2;
    const int q0 = mb * 64;
    const int wr = wid * 16;
    const int gr = lane >> 2, tg = lane & 3;
    const int seg = lane >> 3, r8 = lane & 7;

    const __nv_bfloat16* qh = g_qh + ((size_t)h * S_LEN + q0) * HD;
    const __nv_bfloat16* ql = g_ql + ((size_t)h * S_LEN + q0) * HD;
    const __nv_bfloat16* kh = g_kh + (size_t)kvh * S_LEN * HD;
    const __nv_bfloat16* kl = g_kl + (size_t)kvh * S_LEN * HD;
    const __nv_bfloat16* vh = g_vh + (size_t)kvh * S_LEN * HD;
    const __nv_bfloat16* vl = g_vl + (size_t)kvh * S_LEN * HD;

    auto load_pair = [&](uint32_t dh, uint32_t dl,
                         const __nv_bfloat16* sh, const __nv_bfloat16* sl) {
        #pragma unroll
        for (int i = 0; i < 8; i++) {
            int e = tid + i * 128;
            int r = e >> 4, g = e & 15;
            uint32_t so = (uint32_t)r * 256u + (uint32_t)((g ^ (r & 7)) << 4);
            CP_ASYNC16(dh + so, sh + (size_t)r * HD + g * 8);
            CP_ASYNC16(dl + so, sl + (size_t)r * HD + g * 8);
        }
    };

    load_pair(sb + SQH, sb + SQL, qh, ql);
    load_pair(sb + SKH, sb + SKL, kh, kl);
    load_pair(sb + SVH, sb + SVL, vh, vl);
    CP_COMMIT();
    CP_WAIT0();
    __syncthreads();

    float oacc[16][4] = {};
    const float NEG_INF = -__int_as_float(0x7f800000);
    float m0 = NEG_INF, m1 = NEG_INF, l0 = 0.0f, l1 = 0.0f;

    const int a_row = wr + ((seg & 1) << 3) + r8;
    const int a_gsel = seg >> 1;
    const int b_row_off = ((seg >> 1) << 3) + r8;
    const int b_gsel = seg & 1;
    const int v_row_off = ((seg & 1) << 3) + r8;
    const int v_gsel = seg >> 1;

    for (int kb = 0; kb <= mb; kb++) {
        // ---------------- S = Q K^T (bf16 x3) ----------------
        float sacc[8][4] = {};
        #pragma unroll
        for (int kc = 0; kc < 8; kc++) {
            uint32_t qa_h[4], qa_l[4];
            {
                uint32_t g = (uint32_t)((2 * kc + a_gsel) ^ (a_row & 7));
                uint32_t off = (uint32_t)a_row * 256u + g * 16u;
                LDSM_X4(qa_h[0], qa_h[1], qa_h[2], qa_h[3], sb + SQH + off);
                LDSM_X4(qa_l[0], qa_l[1], qa_l[2], qa_l[3], sb + SQL + off);
            }
            #pragma unroll
            for (int nf2 = 0; nf2 < 4; nf2++) {
                int brow = nf2 * 16 + b_row_off;
                uint32_t g = (uint32_t)((2 * kc + b_gsel) ^ (brow & 7));
                uint32_t off = (uint32_t)brow * 256u + g * 16u;
                uint32_t bh0, bh1, bh2, bh3, bl0, bl1, bl2, bl3;
                LDSM_X4(bh0, bh1, bh2, bh3, sb + SKH + off);
                LDSM_X4(bl0, bl1, bl2, bl3, sb + SKL + off);
                MMA_BF16(sacc[2 * nf2],     qa_h, bh0, bh1);
                MMA_BF16(sacc[2 * nf2],     qa_l, bh0, bh1);
                MMA_BF16(sacc[2 * nf2],     qa_h, bl0, bl1);
                MMA_BF16(sacc[2 * nf2 + 1], qa_h, bh2, bh3);
                MMA_BF16(sacc[2 * nf2 + 1], qa_l, bh2, bh3);
                MMA_BF16(sacc[2 * nf2 + 1], qa_h, bl2, bl3);
            }
        }
        __syncthreads();                      // K tile consumed
        if (kb < mb) {                        // prefetch next K
            load_pair(sb + SKH, sb + SKL,
                      kh + (size_t)(kb + 1) * 64 * HD,
                      kl + (size_t)(kb + 1) * 64 * HD);
            CP_COMMIT();
        }

        // ---------------- online softmax (registers only) ----------------
        const int row0g = q0 + wr + gr;
        const int row1g = row0g + 8;
        if (kb == mb) {
            const int n0 = kb * 64;
            #pragma unroll
            for (int nf = 0; nf < 8; nf++) {
                int c0 = n0 + nf * 8 + 2 * tg;
                if (c0 > row0g)     sacc[nf][0] = NEG_INF;
                if (c0 + 1 > row0g) sacc[nf][1] = NEG_INF;
                if (c0 > row1g)     sacc[nf][2] = NEG_INF;
                if (c0 + 1 > row1g) sacc[nf][3] = NEG_INF;
            }
        }
        float mx0 = NEG_INF, mx1 = NEG_INF;
        #pragma unroll
        for (int nf = 0; nf < 8; nf++) {
            mx0 = fmaxf(mx0, fmaxf(sacc[nf][0], sacc[nf][1]));
            mx1 = fmaxf(mx1, fmaxf(sacc[nf][2], sacc[nf][3]));
        }
        mx0 = fmaxf(mx0, __shfl_xor_sync(0xffffffffu, mx0, 1));
        mx0 = fmaxf(mx0, __shfl_xor_sync(0xffffffffu, mx0, 2));
        mx1 = fmaxf(mx1, __shfl_xor_sync(0xffffffffu, mx1, 1));
        mx1 = fmaxf(mx1, __shfl_xor_sync(0xffffffffu, mx1, 2));
        float mn0 = fmaxf(m0, mx0), mn1 = fmaxf(m1, mx1);
        float rs0 = __expf(m0 - mn0), rs1 = __expf(m1 - mn1);
        float sum0 = 0.0f, sum1 = 0.0f;
        #pragma unroll
        for (int nf = 0; nf < 8; nf++) {
            sacc[nf][0] = __expf(sacc[nf][0] - mn0); sum0 += sacc[nf][0];
            sacc[nf][1] = __expf(sacc[nf][1] - mn0); sum0 += sacc[nf][1];
            sacc[nf][2] = __expf(sacc[nf][2] - mn1); sum1 += sacc[nf][2];
            sacc[nf][3] = __expf(sacc[nf][3] - mn1); sum1 += sacc[nf][3];
        }
        sum0 += __shfl_xor_sync(0xffffffffu, sum0, 1);
        sum0 += __shfl_xor_sync(0xffffffffu, sum0, 2);
        sum1 += __shfl_xor_sync(0xffffffffu, sum1, 1);
        sum1 += __shfl_xor_sync(0xffffffffu, sum1, 2);
        l0 = l0 * rs0 + sum0; m0 = mn0;
        l1 = l1 * rs1 + sum1; m1 = mn1;
        #pragma unroll
        for (int nf = 0; nf < 16; nf++) {
            oacc[nf][0] *= rs0; oacc[nf][1] *= rs0;
            oacc[nf][2] *= rs1; oacc[nf][3] *= rs1;
        }

        // V_kb resident check (load issued last iteration, hidden by QK+softmax)
        if (kb > 0) {
            if (kb < mb) CP_WAIT1(); else CP_WAIT0();
            __syncthreads();
        }

        // ---------------- O += P V (bf16 x3, P from regs) ----------------
        #pragma unroll
        for (int kc2 = 0; kc2 < 4; kc2++) {
            uint32_t pa_h[4], pa_l[4];
            pa_h[0] = pack_bf16_hi(sacc[2 * kc2][0],     sacc[2 * kc2][1]);
            pa_h[1] = pack_bf16_hi(sacc[2 * kc2][2],     sacc[2 * kc2][3]);
            pa_h[2] = pack_bf16_hi(sacc[2 * kc2 + 1][0], sacc[2 * kc2 + 1][1]);
            pa_h[3] = pack_bf16_hi(sacc[2 * kc2 + 1][2], sacc[2 * kc2 + 1][3]);
            pa_l[0] = pack_bf16_lo(sacc[2 * kc2][0],     sacc[2 * kc2][1],     pa_h[0]);
            pa_l[1] = pack_bf16_lo(sacc[2 * kc2][2],     sacc[2 * kc2][3],     pa_h[1]);
            pa_l[2] = pack_bf16_lo(sacc[2 * kc2 + 1][0], sacc[2 * kc2 + 1][1], pa_h[2]);
            pa_l[3] = pack_bf16_lo(sacc[2 * kc2 + 1][2], sacc[2 * kc2 + 1][3], pa_h[3]);
            int krow = 16 * kc2 + v_row_off;
            #pragma unroll
            for (int j = 0; j < 8; j++) {
                uint32_t g = (uint32_t)((2 * j + v_gsel) ^ (krow & 7));
                uint32_t off = (uint32_t)krow * 256u + g * 16u;
                uint32_t vh0, vh1, vh2, vh3, vl0, vl1, vl2, vl3;
                LDSM_X4_T(vh0, vh1, vh2, vh3, sb + SVH + off);
                LDSM_X4_T(vl0, vl1, vl2, vl3, sb + SVL + off);
                MMA_BF16(oacc[2 * j],     pa_h, vh0, vh1);
                MMA_BF16(oacc[2 * j],     pa_l, vh0, vh1);
                MMA_BF16(oacc[2 * j],     pa_h, vl0, vl1);
                MMA_BF16(oacc[2 * j + 1], pa_h, vh2, vh3);
                MMA_BF16(oacc[2 * j + 1], pa_l, vh2, vh3);
                MMA_BF16(oacc[2 * j + 1], pa_h, vl2, vl3);
            }
        }
        __syncthreads();                      // V tile consumed
        if (kb < mb) {
            load_pair(sb + SVH, sb + SVL,
                      vh + (size_t)(kb + 1) * 64 * HD,
                      vl + (size_t)(kb + 1) * 64 * HD);
            CP_COMMIT();
            CP_WAIT1();                       // K_{kb+1} done
            __syncthreads();
        }
    }

    // ---------------- normalize + tf32-round + writeout ----------------
    const float inv0 = 1.0f / l0, inv1 = 1.0f / l1;
    const int row0g = q0 + wr + gr;
    float* dst0 = g_attn + (size_t)row0g * (NH * HD) + h * HD;
    float* dst1 = dst0 + 8 * (size_t)(NH * HD);
    #pragma unroll
    for (int nf = 0; nf < 16; nf++) {
        int col = nf * 8 + 2 * tg;
        *(float2*)(dst0 + col) = make_float2(round_tf32f(oacc[nf][0] * inv0),
                                             round_tf32f(oacc[nf][1] * inv0));
        *(float2*)(dst1 + col) = make_float2(round_tf32f(oacc[nf][2] * inv1),
                                             round_tf32f(oacc[nf][3] * inv1));
    }
}

// ---------------------------------------------------------------------------
extern "C" void kernel_launch(void* const* d_in, const int* in_sizes, int n_in,
                              void* d_out, int out_size) {
    const float* hidden = (const float*)d_in[0];
    const float* w_qkv  = (const float*)d_in[1];
    const float* w_o    = (const float*)d_in[2];
    float* out = (float*)d_out;

    float *attn = nullptr;
    float *hid_r = nullptr, *wqkv_r = nullptr, *wo_r = nullptr;
    cudaGetSymbolAddress((void**)&attn,   g_attn);
    cudaGetSymbolAddress((void**)&hid_r,  g_hid_r);
    cudaGetSymbolAddress((void**)&wqkv_r, g_wqkv_r);
    cudaGetSymbolAddress((void**)&wo_r,   g_wo_r);

    cudaFuncSetAttribute(tmma_gemm_nt, cudaFuncAttributeMaxDynamicSharedMemorySize,
                         GEMM_SMEM_TOTAL);
    cudaFuncSetAttribute(tmma_gemm_qkv_fused,
                         cudaFuncAttributeMaxDynamicSharedMemorySize,
                         GEMM_SMEM_TOTAL);
    cudaFuncSetAttribute(attn_mma, cudaFuncAttributeMaxDynamicSharedMemorySize,
                         ATT_SMEM);

    // 0) tf32 pre-rounding of GEMM operands
    {
        int n4;
        n4 = (QKV_DIM * HIDDEN) / 4;
        round_tf32_kernel<<<(n4 + 255) / 256, 256>>>(w_qkv, wqkv_r, n4);
        n4 = (HIDDEN * NH * HD) / 4;
        round_tf32_kernel<<<(n4 + 255) / 256, 256>>>(w_o, wo_r, n4);
        n4 = (S_LEN * HIDDEN) / 4;
        round_tf32_kernel<<<(n4 + 255) / 256, 256>>>(hidden, hid_r, n4);
    }

    // 1) QKV projection + fused RoPE/scale/bf16-split -> head-major Q/K/V
    tmma_gemm_qkv_fused<<<dim3(S_LEN / TBM, QKV_DIM / TBN), 256, GEMM_SMEM_TOTAL>>>(
        hid_r, wqkv_r);

    // 2) Causal GQA flash attention (bf16 x3 tensor core) -> g_attn (tf32-rounded)
    attn_mma<<<dim3(32, NH), 128, ATT_SMEM>>>();

    // 3) Output projection (tf32 mma): out = g_attn @ w_o^T
    tmma_gemm_nt<<<dim3(S_LEN / TBM, HIDDEN / TBN), 256, GEMM_SMEM_TOTAL>>>(
        attn, wo_r, out, HIDDEN, HIDDEN);
}

// round 16
// speedup vs baseline: 1.1004x; 1.0081x over previous
#include <cuda_runtime.h>
#include <cuda_bf16.h>
#include <cstdint>
#include <math.h>

#define S_LEN   2048
#define HIDDEN  4096
#define NH      32
#define NKVH    8
#define HD      128
#define QKV_DIM 6144      // (32 + 8 + 8) * 128

// Scratch (allocation-free rule: __device__ globals)
__device__ float g_attn[S_LEN * NH * HD];           // tf32-rounded attention out
__device__ float g_hid_r[S_LEN * HIDDEN];           // tf32-rounded hidden
__device__ float g_wqkv_r[QKV_DIM * HIDDEN];        // tf32-rounded w_qkv
__device__ float g_wo_r[HIDDEN * NH * HD];          // tf32-rounded w_o
__device__ __nv_bfloat16 g_qh[NH  * S_LEN * HD];    // [h][s][d]
__device__ __nv_bfloat16 g_ql[NH  * S_LEN * HD];
__device__ __nv_bfloat16 g_kh[NKVH * S_LEN * HD];
__device__ __nv_bfloat16 g_kl[NKVH * S_LEN * HD];
__device__ __nv_bfloat16 g_vh[NKVH * S_LEN * HD];
__device__ __nv_bfloat16 g_vl[NKVH * S_LEN * HD];

__device__ __forceinline__ uint32_t smem_to_u32(const void* smem_ptr) {
    uint32_t addr;
    asm("{ .reg .u64 tmp; cvta.to.shared.u64 tmp, %1; cvt.u32.u64 %0, tmp; }"
        : "=r"(addr) : "l"(smem_ptr));
    return addr;
}

#define LDSM_X4(r0, r1, r2, r3, addr) \
    asm volatile("ldmatrix.sync.aligned.m8n8.x4.shared.b16 {%0,%1,%2,%3}, [%4];" \
                 : "=r"(r0), "=r"(r1), "=r"(r2), "=r"(r3) : "r"(addr))

#define LDSM_X4_T(r0, r1, r2, r3, addr) \
    asm volatile("ldmatrix.sync.aligned.m8n8.x4.trans.shared.b16 {%0,%1,%2,%3}, [%4];" \
                 : "=r"(r0), "=r"(r1), "=r"(r2), "=r"(r3) : "r"(addr))

__device__ __forceinline__ float round_tf32f(float x) {
    uint32_t u;
    asm("cvt.rna.tf32.f32 %0, %1;" : "=r"(u) : "f"(x));
    return __uint_as_float(u);
}

#define MMA_TF32(d, a0, a1, a2, a3, b0, b1) \
    asm volatile("mma.sync.aligned.m16n8k8.row.col.f32.tf32.tf32.f32 " \
                 "{%0,%1,%2,%3}, {%4,%5,%6,%7}, {%8,%9}, {%0,%1,%2,%3};" \
                 : "+f"((d)[0]), "+f"((d)[1]), "+f"((d)[2]), "+f"((d)[3]) \
                 : "r"(a0), "r"(a1), "r"(a2), "r"(a3), "r"(b0), "r"(b1))

#define MMA_BF16(d, a, b0, b1) \
    asm volatile("mma.sync.aligned.m16n8k16.row.col.f32.bf16.bf16.f32 " \
                 "{%0,%1,%2,%3}, {%4,%5,%6,%7}, {%8,%9}, {%0,%1,%2,%3};" \
                 : "+f"((d)[0]), "+f"((d)[1]), "+f"((d)[2]), "+f"((d)[3]) \
                 : "r"((a)[0]), "r"((a)[1]), "r"((a)[2]), "r"((a)[3]), \
                   "r"(b0), "r"(b1))

#define CP_ASYNC16(dst, src) \
    asm volatile("cp.async.cg.shared.global [%0], [%1], 16;" \
                 :: "r"(dst), "l"(src) : "memory")
#define CP_COMMIT()  asm volatile("cp.async.commit_group;" ::: "memory")
#define CP_WAIT0()   asm volatile("cp.async.wait_group 0;" ::: "memory")
#define CP_WAIT1()   asm volatile("cp.async.wait_group 1;" ::: "memory")

__device__ __forceinline__ uint32_t pack_bf16_hi(float x, float y) {
    __nv_bfloat162 t = __floats2bfloat162_rn(x, y);
    return *reinterpret_cast<uint32_t*>(&t);
}
__device__ __forceinline__ uint32_t pack_bf16_lo(float x, float y, uint32_t hi) {
    __nv_bfloat162 h = *reinterpret_cast<__nv_bfloat162*>(&hi);
    __nv_bfloat162 t = __floats2bfloat162_rn(x - __bfloat162float(h.x),
                                             y - __bfloat162float(h.y));
    return *reinterpret_cast<uint32_t*>(&t);
}

// ===========================================================================
// Merged tf32 pre-rounding pass: w_qkv, w_o, hidden in ONE launch.
// ===========================================================================
__global__ void __launch_bounds__(256) round3_tf32_kernel(
        const float* __restrict__ s1, float* __restrict__ d1, int n1,
        const float* __restrict__ s2, float* __restrict__ d2, int n2,
        const float* __restrict__ s3, float* __restrict__ d3, int n3) {
    int i = blockIdx.x * blockDim.x + threadIdx.x;
    const float* s; float* d; int j;
    if (i < n1)            { s = s1; d = d1; j = i; }
    else if (i < n1 + n2)  { s = s2; d = d2; j = i - n1; }
    else if (i < n1 + n2 + n3) { s = s3; d = d3; j = i - n1 - n2; }
    else return;
    float4 v = ((const float4*)s)[j];
    v.x = round_tf32f(v.x);
    v.y = round_tf32f(v.y);
    v.z = round_tf32f(v.z);
    v.w = round_tf32f(v.w);
    ((float4*)d)[j] = v;
}

// ===========================================================================
// Shared GEMM mainloop config — R12-proven optimum:
// 128x128 CTA tile, BK=32, 256 threads, 8 warps 2(M)x4(N), 64x32 warp tile,
// 3-stage cp.async, single barrier per chunk, 2 CTAs/SM.
// ===========================================================================
#define TBM 128
#define TBN 128
#define TBK 32
#define TILE_BYTES (TBM * TBK * 4)       // 16384
#define STAGE_BYTES (2 * TILE_BYTES)     // A+B per stage = 32768
#define NSTAGE 3
#define GEMM_SMEM_TOTAL (NSTAGE * STAGE_BYTES)   // 98304
#define EP_STRIDE 132                    // epilogue staging row stride (floats)

#define GEMM_MAINLOOP(A_PTR, B_PTR, KDIM)                                      \
    const int lrr = tid >> 3, lcj = tid & 7;                                   \
    auto load_chunk = [&](int c, int stg) {                                    \
        const uint32_t sA = sbase + (uint32_t)stg * STAGE_BYTES;               \
        const uint32_t sB = sA + TILE_BYTES;                                   \
        const int k0 = c * TBK;                                                \
        _Pragma("unroll")                                                      \
        for (int i = 0; i < 4; i++) {                                          \
            int rr = lrr + i * 32;                                             \
            uint32_t so = (uint32_t)rr * 128u + (uint32_t)((lcj ^ (rr & 7)) << 4); \
            const float* gA = (A_PTR) + (size_t)(row0 + rr) * (KDIM) + k0 + lcj * 4; \
            const float* gB = (B_PTR) + (size_t)(col0 + rr) * (KDIM) + k0 + lcj * 4; \
            CP_ASYNC16(sA + so, gA);                                           \
            CP_ASYNC16(sB + so, gB);                                           \
        }                                                                      \
        CP_COMMIT();                                                           \
    };                                                                         \
    load_chunk(0, 0);                                                          \
    load_chunk(1, 1);                                                          \
    int st = 0;                                                                \
    const int NCHUNK = (KDIM) / TBK;                                           \
    for (int c = 0; c < NCHUNK; c++) {                                         \
        if (c < NCHUNK - 1) CP_WAIT1(); else CP_WAIT0();                       \
        __syncthreads();                                                       \
        if (c + 2 < NCHUNK) {                                                  \
            int st2 = st + 2; if (st2 >= NSTAGE) st2 -= NSTAGE;                \
            load_chunk(c + 2, st2);                                            \
        }                                                                      \
        const uint32_t sA = sbase + (uint32_t)st * STAGE_BYTES;                \
        const uint32_t sB = sA + TILE_BYTES;                                   \
        _Pragma("unroll")                                                      \
        for (int ks = 0; ks < 4; ks++) {                                       \
            uint32_t a[4][4], b[2][4];                                         \
            _Pragma("unroll")                                                  \
            for (int mf = 0; mf < 4; mf++) {                                   \
                int row = warp_m * 64 + mf * 16 + a_row_off;                   \
                uint32_t g = (uint32_t)((ks * 2 + a_kh) ^ (row & 7));          \
                uint32_t addr = sA + (uint32_t)row * 128u + g * 16u;           \
                LDSM_X4(a[mf][0], a[mf][1], a[mf][2], a[mf][3], addr);         \
            }                                                                  \
            _Pragma("unroll")                                                  \
            for (int nf2 = 0; nf2 < 2; nf2++) {                                \
                int row = warp_n * 32 + nf2 * 16 + b_row_off;                  \
                uint32_t g = (uint32_t)((ks * 2 + b_kh) ^ (row & 7));          \
                uint32_t addr = sB + (uint32_t)row * 128u + g * 16u;           \
                LDSM_X4(b[nf2][0], b[nf2][1], b[nf2][2], b[nf2][3], addr);     \
            }                                                                  \
            _Pragma("unroll")                                                  \
            for (int mf = 0; mf < 4; mf++)                                     \
                _Pragma("unroll")                                              \
                for (int nf = 0; nf < 4; nf++) {                               \
                    uint32_t bb0 = b[nf >> 1][(nf & 1) * 2 + 0];               \
                    uint32_t bb1 = b[nf >> 1][(nf & 1) * 2 + 1];               \
                    MMA_TF32(acc[mf][nf], a[mf][0], a[mf][1], a[mf][2],        \
                             a[mf][3], bb0, bb1);                              \
                }                                                              \
        }                                                                      \
        if (++st >= NSTAGE) st = 0;                                            \
    }

// ---------------------------------------------------------------------------
// Generic GEMM NT (used for O projection): C = A * B^T
// ---------------------------------------------------------------------------
__global__ void __launch_bounds__(256) tmma_gemm_nt(const float* __restrict__ A,
                                                    const float* __restrict__ B,
                                                    float* __restrict__ C,
                                                    int N, int K) {
    extern __shared__ char smem[];
    const uint32_t sbase = smem_to_u32(smem);
    const int tid = threadIdx.x;
    const int lane = tid & 31;
    const int wid = tid >> 5;
    const int warp_m = wid & 1;
    const int warp_n = wid >> 1;
    const int row0 = blockIdx.x * TBM;
    const int col0 = blockIdx.y * TBN;

    const int seg = lane >> 3, r8 = lane & 7;
    const int a_row_off = ((seg & 1) << 3) + r8;
    const int a_kh = seg >> 1;
    const int b_row_off = ((seg >> 1) << 3) + r8;
    const int b_kh = seg & 1;

    float acc[4][4][4] = {};

    GEMM_MAINLOOP(A, B, K)

    #pragma unroll
    for (int mf = 0; mf < 4; mf++) {
        int grow = row0 + warp_m * 64 + mf * 16 + (lane >> 2);
        #pragma unroll
        for (int nf = 0; nf < 4; nf++) {
            int gcol = col0 + warp_n * 32 + nf * 8 + ((lane & 3) << 1);
            *(float2*)(C + (size_t)grow * N + gcol) =
                make_float2(acc[mf][nf][0], acc[mf][nf][1]);
            *(float2*)(C + (size_t)(grow + 8) * N + gcol) =
                make_float2(acc[mf][nf][2], acc[mf][nf][3]);
        }
    }
}

// ---------------------------------------------------------------------------
// QKV GEMM with FUSED RoPE + scale + bf16 hi/lo split epilogue (R15-proven).
// ---------------------------------------------------------------------------
__global__ void __launch_bounds__(256) tmma_gemm_qkv_fused(const float* __restrict__ A,
                                                           const float* __restrict__ B) {
    extern __shared__ char smem[];
    const uint32_t sbase = smem_to_u32(smem);
    const int tid = threadIdx.x;
    const int lane = tid & 31;
    const int wid = tid >> 5;
    const int warp_m = wid & 1;
    const int warp_n = wid >> 1;
    const int row0 = blockIdx.x * TBM;
    const int col0 = blockIdx.y * TBN;
    const int hh = blockIdx.y;           // head region (tile = one head)

    const int seg = lane >> 3, r8 = lane & 7;
    const int a_row_off = ((seg & 1) << 3) + r8;
    const int a_kh = seg >> 1;
    const int b_row_off = ((seg >> 1) << 3) + r8;
    const int b_kh = seg & 1;

    float acc[4][4][4] = {};

    GEMM_MAINLOOP(A, B, HIDDEN)

    // ---- epilogue: stage acc tile in smem (pipeline buffers are free) ----
    __syncthreads();
    float* T = (float*)smem;              // [128][EP_STRIDE]
    #pragma unroll
    for (int mf = 0; mf < 4; mf++) {
        int r = warp_m * 64 + mf * 16 + (lane >> 2);
        #pragma unroll
        for (int nf = 0; nf < 4; nf++) {
            int cc = warp_n * 32 + nf * 8 + ((lane & 3) << 1);
            *(float2*)(T + r * EP_STRIDE + cc) =
                make_float2(acc[mf][nf][0], acc[mf][nf][1]);
            *(float2*)(T + (r + 8) * EP_STRIDE + cc) =
                make_float2(acc[mf][nf][2], acc[mf][nf][3]);
        }
    }
    __syncthreads();

    __nv_bfloat16 *base_h, *base_l;
    int head;
    if (hh < 32)      { base_h = g_qh; base_l = g_ql; head = hh; }
    else if (hh < 40) { base_h = g_kh; base_l = g_kl; head = hh - 32; }
    else              { base_h = g_vh; base_l = g_vl; head = hh - 40; }
    const bool do_rope  = (hh < 40);
    const bool do_scale = (hh < 32);

    #pragma unroll 4
    for (int i = 0; i < 32; i++) {
        int e = tid + i * 256;            // 0..8191
        int r = e >> 6;                   // 0..127
        int d = e & 63;                   // 0..63
        float x1 = T[r * EP_STRIDE + d];
        float x2 = T[r * EP_STRIDE + d + 64];
        int s = row0 + r;

        float o1 = x1, o2 = x2;
        if (do_rope) {
            float freq = exp2f(-0.20762050593046013f * (float)d);
            float ang = (float)s * freq;
            float sn, cs;
            sincosf(ang, &sn, &cs);
            o1 = x1 * cs - x2 * sn;
            o2 = x1 * sn + x2 * cs;
        }
        if (do_scale) {
            const float scale = 0.08838834764831845f;   // 1/sqrt(128)
            o1 *= scale; o2 *= scale;
        }
        __nv_bfloat16 h1 = __float2bfloat16_rn(o1);
        __nv_bfloat16 h2 = __float2bfloat16_rn(o2);
        size_t off = ((size_t)head * S_LEN + s) * HD + d;
        base_h[off]      = h1;
        base_h[off + 64] = h2;
        base_l[off]      = __float2bfloat16_rn(o1 - __bfloat162float(h1));
        base_l[off + 64] = __float2bfloat16_rn(o2 - __bfloat162float(h2));
    }
}

// ===========================================================================
// Tensor-core flash attention, bf16 3-term compensated.
// RESTRUCTURED barriers: 3 per KV tile (was 4). FIFO: commit K then V each
// iteration; top-of-loop wait_group(1)+sync = K_kb ready; mid wait_group(0)
// +sync = V_kb ready AND all warps done reading K (so K prefetch is safe);
// post-PV sync = V buffer free. Data-op order unchanged -> bit-identical.
// ===========================================================================
#define ATT_SMEM (6 * 64 * 128 * 2)    // 98304 bytes
#define SQH 0
#define SQL 16384
#define SKH 32768
#define SKL 49152
#define SVH 65536
#define SVL 81920

__global__ void __launch_bounds__(128, 2) attn_mma() {
    extern __shared__ char smem[];
    const uint32_t sb = smem_to_u32(smem);
    const int tid = threadIdx.x;
    const int lane = tid & 31;
    const int wid = tid >> 5;
    const int mb = 31 - (int)blockIdx.x;     // heaviest first
    const int h = blockIdx.y;
    const int kvh = h >> 2;
    const int q0 = mb * 64;
    const int wr = wid * 16;
    const int gr = lane >> 2, tg = lane & 3;
    const int seg = lane >> 3, r8 = lane & 7;

    const __nv_bfloat16* qh = g_qh + ((size_t)h * S_LEN + q0) * HD;
    const __nv_bfloat16* ql = g_ql + ((size_t)h * S_LEN + q0) * HD;
    const __nv_bfloat16* kh = g_kh + (size_t)kvh * S_LEN * HD;
    const __nv_bfloat16* kl = g_kl + (size_t)kvh * S_LEN * HD;
    const __nv_bfloat16* vh = g_vh + (size_t)kvh * S_LEN * HD;
    const __nv_bfloat16* vl = g_vl + (size_t)kvh * S_LEN * HD;

    auto load_pair = [&](uint32_t dh, uint32_t dl,
                         const __nv_bfloat16* sh, const __nv_bfloat16* sl) {
        #pragma unroll
        for (int i = 0; i < 8; i++) {
            int e = tid + i * 128;
            int r = e >> 4, g = e & 15;
            uint32_t so = (uint32_t)r * 256u + (uint32_t)((g ^ (r & 7)) << 4);
            CP_ASYNC16(dh + so, sh + (size_t)r * HD + g * 8);
            CP_ASYNC16(dl + so, sl + (size_t)r * HD + g * 8);
        }
    };

    load_pair(sb + SQH, sb + SQL, qh, ql);
    load_pair(sb + SKH, sb + SKL, kh, kl);
    load_pair(sb + SVH, sb + SVL, vh, vl);
    CP_COMMIT();
    CP_WAIT0();
    __syncthreads();

    float oacc[16][4] = {};
    const float NEG_INF = -__int_as_float(0x7f800000);
    float m0 = NEG_INF, m1 = NEG_INF, l0 = 0.0f, l1 = 0.0f;

    const int a_row = wr + ((seg & 1) << 3) + r8;
    const int a_gsel = seg >> 1;
    const int b_row_off = ((seg >> 1) << 3) + r8;
    const int b_gsel = seg & 1;
    const int v_row_off = ((seg & 1) << 3) + r8;
    const int v_gsel = seg >> 1;

    for (int kb = 0; kb <= mb; kb++) {
        if (kb > 0) {
            CP_WAIT1();                   // K_kb resident (V_kb may be in flight)
            __syncthreads();
        }

        // ---------------- S = Q K^T (bf16 x3) ----------------
        float sacc[8][4] = {};
        #pragma unroll
        for (int kc = 0; kc < 8; kc++) {
            uint32_t qa_h[4], qa_l[4];
            {
                uint32_t g = (uint32_t)((2 * kc + a_gsel) ^ (a_row & 7));
                uint32_t off = (uint32_t)a_row * 256u + g * 16u;
                LDSM_X4(qa_h[0], qa_h[1], qa_h[2], qa_h[3], sb + SQH + off);
                LDSM_X4(qa_l[0], qa_l[1], qa_l[2], qa_l[3], sb + SQL + off);
            }
            #pragma unroll
            for (int nf2 = 0; nf2 < 4; nf2++) {
                int brow = nf2 * 16 + b_row_off;
                uint32_t g = (uint32_t)((2 * kc + b_gsel) ^ (brow & 7));
                uint32_t off = (uint32_t)brow * 256u + g * 16u;
                uint32_t bh0, bh1, bh2, bh3, bl0, bl1, bl2, bl3;
                LDSM_X4(bh0, bh1, bh2, bh3, sb + SKH + off);
                LDSM_X4(bl0, bl1, bl2, bl3, sb + SKL + off);
                MMA_BF16(sacc[2 * nf2],     qa_h, bh0, bh1);
                MMA_BF16(sacc[2 * nf2],     qa_l, bh0, bh1);
                MMA_BF16(sacc[2 * nf2],     qa_h, bl0, bl1);
                MMA_BF16(sacc[2 * nf2 + 1], qa_h, bh2, bh3);
                MMA_BF16(sacc[2 * nf2 + 1], qa_l, bh2, bh3);
                MMA_BF16(sacc[2 * nf2 + 1], qa_h, bl2, bl3);
            }
        }

        // ---------------- online softmax (registers only) ----------------
        const int row0g = q0 + wr + gr;
        const int row1g = row0g + 8;
        if (kb == mb) {
            const int n0 = kb * 64;
            #pragma unroll
            for (int nf = 0; nf < 8; nf++) {
                int c0 = n0 + nf * 8 + 2 * tg;
                if (c0 > row0g)     sacc[nf][0] = NEG_INF;
                if (c0 + 1 > row0g) sacc[nf][1] = NEG_INF;
                if (c0 > row1g)     sacc[nf][2] = NEG_INF;
                if (c0 + 1 > row1g) sacc[nf][3] = NEG_INF;
            }
        }
        float mx0 = NEG_INF, mx1 = NEG_INF;
        #pragma unroll
        for (int nf = 0; nf < 8; nf++) {
            mx0 = fmaxf(mx0, fmaxf(sacc[nf][0], sacc[nf][1]));
            mx1 = fmaxf(mx1, fmaxf(sacc[nf][2], sacc[nf][3]));
        }
        mx0 = fmaxf(mx0, __shfl_xor_sync(0xffffffffu, mx0, 1));
        mx0 = fmaxf(mx0, __shfl_xor_sync(0xffffffffu, mx0, 2));
        mx1 = fmaxf(mx1, __shfl_xor_sync(0xffffffffu, mx1, 1));
        mx1 = fmaxf(mx1, __shfl_xor_sync(0xffffffffu, mx1, 2));
        float mn0 = fmaxf(m0, mx0), mn1 = fmaxf(m1, mx1);
        float rs0 = __expf(m0 - mn0), rs1 = __expf(m1 - mn1);
        float sum0 = 0.0f, sum1 = 0.0f;
        #pragma unroll
        for (int nf = 0; nf < 8; nf++) {
            sacc[nf][0] = __expf(sacc[nf][0] - mn0); sum0 += sacc[nf][0];
            sacc[nf][1] = __expf(sacc[nf][1] - mn0); sum0 += sacc[nf][1];
            sacc[nf][2] = __expf(sacc[nf][2] - mn1); sum1 += sacc[nf][2];
            sacc[nf][3] = __expf(sacc[nf][3] - mn1); sum1 += sacc[nf][3];
        }
        sum0 += __shfl_xor_sync(0xffffffffu, sum0, 1);
        sum0 += __shfl_xor_sync(0xffffffffu, sum0, 2);
        sum1 += __shfl_xor_sync(0xffffffffu, sum1, 1);
        sum1 += __shfl_xor_sync(0xffffffffu, sum1, 2);
        l0 = l0 * rs0 + sum0; m0 = mn0;
        l1 = l1 * rs1 + sum1; m1 = mn1;
        #pragma unroll
        for (int nf = 0; nf < 16; nf++) {
            oacc[nf][0] *= rs0; oacc[nf][1] *= rs0;
            oacc[nf][2] *= rs1; oacc[nf][3] *= rs1;
        }

        // V_kb resident to all + all warps done reading K (enables K prefetch)
        CP_WAIT0();
        __syncthreads();
        if (kb < mb) {                    // prefetch next K into freed K buffer
            load_pair(sb + SKH, sb + SKL,
                      kh + (size_t)(kb + 1) * 64 * HD,
                      kl + (size_t)(kb + 1) * 64 * HD);
            CP_COMMIT();
        }

        // ---------------- O += P V (bf16 x3, P from regs) ----------------
        #pragma unroll
        for (int kc2 = 0; kc2 < 4; kc2++) {
            uint32_t pa_h[4], pa_l[4];
            pa_h[0] = pack_bf16_hi(sacc[2 * kc2][0],     sacc[2 * kc2][1]);
            pa_h[1] = pack_bf16_hi(sacc[2 * kc2][2],     sacc[2 * kc2][3]);
            pa_h[2] = pack_bf16_hi(sacc[2 * kc2 + 1][0], sacc[2 * kc2 + 1][1]);
            pa_h[3] = pack_bf16_hi(sacc[2 * kc2 + 1][2], sacc[2 * kc2 + 1][3]);
            pa_l[0] = pack_bf16_lo(sacc[2 * kc2][0],     sacc[2 * kc2][1],     pa_h[0]);
            pa_l[1] = pack_bf16_lo(sacc[2 * kc2][2],     sacc[2 * kc2][3],     pa_h[1]);
            pa_l[2] = pack_bf16_lo(sacc[2 * kc2 + 1][0], sacc[2 * kc2 + 1][1], pa_h[2]);
            pa_l[3] = pack_bf16_lo(sacc[2 * kc2 + 1][2], sacc[2 * kc2 + 1][3], pa_h[3]);
            int krow = 16 * kc2 + v_row_off;
            #pragma unroll
            for (int j = 0; j < 8; j++) {
                uint32_t g = (uint32_t)((2 * j + v_gsel) ^ (krow & 7));
                uint32_t off = (uint32_t)krow * 256u + g * 16u;
                uint32_t vh0, vh1, vh2, vh3, vl0, vl1, vl2, vl3;
                LDSM_X4_T(vh0, vh1, vh2, vh3, sb + SVH + off);
                LDSM_X4_T(vl0, vl1, vl2, vl3, sb + SVL + off);
                MMA_BF16(oacc[2 * j],     pa_h, vh0, vh1);
                MMA_BF16(oacc[2 * j],     pa_l, vh0, vh1);
                MMA_BF16(oacc[2 * j],     pa_h, vl0, vl1);
                MMA_BF16(oacc[2 * j + 1], pa_h, vh2, vh3);
                MMA_BF16(oacc[2 * j + 1], pa_l, vh2, vh3);
                MMA_BF16(oacc[2 * j + 1], pa_h, vl2, vl3);
            }
        }
        __syncthreads();                  // V buffer free
        if (kb < mb) {                    // prefetch next V (commit AFTER K)
            load_pair(sb + SVH, sb + SVL,
                      vh + (size_t)(kb + 1) * 64 * HD,
                      vl + (size_t)(kb + 1) * 64 * HD);
            CP_COMMIT();
        }
    }

    // ---------------- normalize + tf32-round + writeout ----------------
    const float inv0 = 1.0f / l0, inv1 = 1.0f / l1;
    const int row0g = q0 + wr + gr;
    float* dst0 = g_attn + (size_t)row0g * (NH * HD) + h * HD;
    float* dst1 = dst0 + 8 * (size_t)(NH * HD);
    #pragma unroll
    for (int nf = 0; nf < 16; nf++) {
        int col = nf * 8 + 2 * tg;
        *(float2*)(dst0 + col) = make_float2(round_tf32f(oacc[nf][0] * inv0),
                                             round_tf32f(oacc[nf][1] * inv0));
        *(float2*)(dst1 + col) = make_float2(round_tf32f(oacc[nf][2] * inv1),
                                             round_tf32f(oacc[nf][3] * inv1));
    }
}

// ---------------------------------------------------------------------------
extern "C" void kernel_launch(void* const* d_in, const int* in_sizes, int n_in,
                              void* d_out, int out_size) {
    const float* hidden = (const float*)d_in[0];
    const float* w_qkv  = (const float*)d_in[1];
    const float* w_o    = (const float*)d_in[2];
    float* out = (float*)d_out;

    float *attn = nullptr;
    float *hid_r = nullptr, *wqkv_r = nullptr, *wo_r = nullptr;
    cudaGetSymbolAddress((void**)&attn,   g_attn);
    cudaGetSymbolAddress((void**)&hid_r,  g_hid_r);
    cudaGetSymbolAddress((void**)&wqkv_r, g_wqkv_r);
    cudaGetSymbolAddress((void**)&wo_r,   g_wo_r);

    cudaFuncSetAttribute(tmma_gemm_nt, cudaFuncAttributeMaxDynamicSharedMemorySize,
                         GEMM_SMEM_TOTAL);
    cudaFuncSetAttribute(tmma_gemm_qkv_fused,
                         cudaFuncAttributeMaxDynamicSharedMemorySize,
                         GEMM_SMEM_TOTAL);
    cudaFuncSetAttribute(attn_mma, cudaFuncAttributeMaxDynamicSharedMemorySize,
                         ATT_SMEM);

    // 0) merged tf32 pre-rounding of all GEMM operands (single launch)
    {
        const int n1 = (QKV_DIM * HIDDEN) / 4;
        const int n2 = (HIDDEN * NH * HD) / 4;
        const int n3 = (S_LEN * HIDDEN) / 4;
        const int nt = n1 + n2 + n3;
        round3_tf32_kernel<<<(nt + 255) / 256, 256>>>(w_qkv, wqkv_r, n1,
                                                      w_o, wo_r, n2,
                                                      hidden, hid_r, n3);
    }

    // 1) QKV projection + fused RoPE/scale/bf16-split -> head-major Q/K/V
    tmma_gemm_qkv_fused<<<dim3(S_LEN / TBM, QKV_DIM / TBN), 256, GEMM_SMEM_TOTAL>>>(
        hid_r, wqkv_r);

    // 2) Causal GQA flash attention (bf16 x3 tensor core) -> g_attn (tf32-rounded)
    attn_mma<<<dim3(32, NH), 128, ATT_SMEM>>>();

    // 3) Output projection (tf32 mma): out = g_attn @ w_o^T
    tmma_gemm_nt<<<dim3(S_LEN / TBM, HIDDEN / TBN), 256, GEMM_SMEM_TOTAL>>>(
        attn, wo_r, out, HIDDEN, HIDDEN);
}

// round 17
// speedup vs baseline: 1.1012x; 1.0007x over previous
#include <cuda_runtime.h>
#include <cuda_bf16.h>
#include <cstdint>
#include <math.h>

#define S_LEN   2048
#define HIDDEN  4096
#define NH      32
#define NKVH    8
#define HD      128
#define QKV_DIM 6144      // (32 + 8 + 8) * 128

// Scratch (allocation-free rule: __device__ globals)
__device__ float g_attn[S_LEN * NH * HD];           // tf32-rounded attention out
__device__ float g_hid_r[S_LEN * HIDDEN];           // tf32-rounded hidden
__device__ float g_wqkv_r[QKV_DIM * HIDDEN];        // tf32-rounded w_qkv
__device__ float g_wo_r[HIDDEN * NH * HD];          // tf32-rounded w_o
__device__ __nv_bfloat16 g_qh[NH  * S_LEN * HD];    // [h][s][d]
__device__ __nv_bfloat16 g_ql[NH  * S_LEN * HD];
__device__ __nv_bfloat16 g_kh[NKVH * S_LEN * HD];
__device__ __nv_bfloat16 g_kl[NKVH * S_LEN * HD];
__device__ __nv_bfloat16 g_vh[NKVH * S_LEN * HD];
__device__ __nv_bfloat16 g_vl[NKVH * S_LEN * HD];

__device__ __forceinline__ uint32_t smem_to_u32(const void* smem_ptr) {
    uint32_t addr;
    asm("{ .reg .u64 tmp; cvta.to.shared.u64 tmp, %1; cvt.u32.u64 %0, tmp; }"
        : "=r"(addr) : "l"(smem_ptr));
    return addr;
}

#define LDSM_X4(r0, r1, r2, r3, addr) \
    asm volatile("ldmatrix.sync.aligned.m8n8.x4.shared.b16 {%0,%1,%2,%3}, [%4];" \
                 : "=r"(r0), "=r"(r1), "=r"(r2), "=r"(r3) : "r"(addr))

#define LDSM_X4_T(r0, r1, r2, r3, addr) \
    asm volatile("ldmatrix.sync.aligned.m8n8.x4.trans.shared.b16 {%0,%1,%2,%3}, [%4];" \
                 : "=r"(r0), "=r"(r1), "=r"(r2), "=r"(r3) : "r"(addr))

__device__ __forceinline__ float round_tf32f(float x) {
    uint32_t u;
    asm("cvt.rna.tf32.f32 %0, %1;" : "=r"(u) : "f"(x));
    return __uint_as_float(u);
}

#define MMA_TF32(d, a0, a1, a2, a3, b0, b1) \
    asm volatile("mma.sync.aligned.m16n8k8.row.col.f32.tf32.tf32.f32 " \
                 "{%0,%1,%2,%3}, {%4,%5,%6,%7}, {%8,%9}, {%0,%1,%2,%3};" \
                 : "+f"((d)[0]), "+f"((d)[1]), "+f"((d)[2]), "+f"((d)[3]) \
                 : "r"(a0), "r"(a1), "r"(a2), "r"(a3), "r"(b0), "r"(b1))

#define MMA_BF16(d, a, b0, b1) \
    asm volatile("mma.sync.aligned.m16n8k16.row.col.f32.bf16.bf16.f32 " \
                 "{%0,%1,%2,%3}, {%4,%5,%6,%7}, {%8,%9}, {%0,%1,%2,%3};" \
                 : "+f"((d)[0]), "+f"((d)[1]), "+f"((d)[2]), "+f"((d)[3]) \
                 : "r"((a)[0]), "r"((a)[1]), "r"((a)[2]), "r"((a)[3]), \
                   "r"(b0), "r"(b1))

#define CP_ASYNC16(dst, src) \
    asm volatile("cp.async.cg.shared.global [%0], [%1], 16;" \
                 :: "r"(dst), "l"(src) : "memory")
#define CP_COMMIT()  asm volatile("cp.async.commit_group;" ::: "memory")
#define CP_WAIT0()   asm volatile("cp.async.wait_group 0;" ::: "memory")
#define CP_WAIT1()   asm volatile("cp.async.wait_group 1;" ::: "memory")

__device__ __forceinline__ uint32_t pack_bf16_hi(float x, float y) {
    __nv_bfloat162 t = __floats2bfloat162_rn(x, y);
    return *reinterpret_cast<uint32_t*>(&t);
}
__device__ __forceinline__ uint32_t pack_bf16_lo(float x, float y, uint32_t hi) {
    __nv_bfloat162 h = *reinterpret_cast<__nv_bfloat162*>(&hi);
    __nv_bfloat162 t = __floats2bfloat162_rn(x - __bfloat162float(h.x),
                                             y - __bfloat162float(h.y));
    return *reinterpret_cast<uint32_t*>(&t);
}

// ===========================================================================
// Merged tf32 pre-rounding pass: w_qkv, w_o, hidden in ONE launch.
// ===========================================================================
__global__ void __launch_bounds__(256) round3_tf32_kernel(
        const float* __restrict__ s1, float* __restrict__ d1, int n1,
        const float* __restrict__ s2, float* __restrict__ d2, int n2,
        const float* __restrict__ s3, float* __restrict__ d3, int n3) {
    int i = blockIdx.x * blockDim.x + threadIdx.x;
    const float* s; float* d; int j;
    if (i < n1)            { s = s1; d = d1; j = i; }
    else if (i < n1 + n2)  { s = s2; d = d2; j = i - n1; }
    else if (i < n1 + n2 + n3) { s = s3; d = d3; j = i - n1 - n2; }
    else return;
    float4 v = ((const float4*)s)[j];
    v.x = round_tf32f(v.x);
    v.y = round_tf32f(v.y);
    v.z = round_tf32f(v.z);
    v.w = round_tf32f(v.w);
    ((float4*)d)[j] = v;
}

// ===========================================================================
// Shared GEMM mainloop config — R12-proven optimum:
// 128x128 CTA tile, BK=32, 256 threads, 8 warps 2(M)x4(N), 64x32 warp tile,
// 3-stage cp.async, single barrier per chunk, 2 CTAs/SM.
// ===========================================================================
#define TBM 128
#define TBN 128
#define TBK 32
#define TILE_BYTES (TBM * TBK * 4)       // 16384
#define STAGE_BYTES (2 * TILE_BYTES)     // A+B per stage = 32768
#define NSTAGE 3
#define GEMM_SMEM_TOTAL (NSTAGE * STAGE_BYTES)   // 98304
#define EP_STRIDE 132                    // epilogue staging row stride (floats)

#define GEMM_MAINLOOP(A_PTR, B_PTR, KDIM)                                      \
    const int lrr = tid >> 3, lcj = tid & 7;                                   \
    auto load_chunk = [&](int c, int stg) {                                    \
        const uint32_t sA = sbase + (uint32_t)stg * STAGE_BYTES;               \
        const uint32_t sB = sA + TILE_BYTES;                                   \
        const int k0 = c * TBK;                                                \
        _Pragma("unroll")                                                      \
        for (int i = 0; i < 4; i++) {                                          \
            int rr = lrr + i * 32;                                             \
            uint32_t so = (uint32_t)rr * 128u + (uint32_t)((lcj ^ (rr & 7)) << 4); \
            const float* gA = (A_PTR) + (size_t)(row0 + rr) * (KDIM) + k0 + lcj * 4; \
            const float* gB = (B_PTR) + (size_t)(col0 + rr) * (KDIM) + k0 + lcj * 4; \
            CP_ASYNC16(sA + so, gA);                                           \
            CP_ASYNC16(sB + so, gB);                                           \
        }                                                                      \
        CP_COMMIT();                                                           \
    };                                                                         \
    load_chunk(0, 0);                                                          \
    load_chunk(1, 1);                                                          \
    int st = 0;                                                                \
    const int NCHUNK = (KDIM) / TBK;                                           \
    for (int c = 0; c < NCHUNK; c++) {                                         \
        if (c < NCHUNK - 1) CP_WAIT1(); else CP_WAIT0();                       \
        __syncthreads();                                                       \
        if (c + 2 < NCHUNK) {                                                  \
            int st2 = st + 2; if (st2 >= NSTAGE) st2 -= NSTAGE;                \
            load_chunk(c + 2, st2);                                            \
        }                                                                      \
        const uint32_t sA = sbase + (uint32_t)st * STAGE_BYTES;                \
        const uint32_t sB = sA + TILE_BYTES;                                   \
        _Pragma("unroll")                                                      \
        for (int ks = 0; ks < 4; ks++) {                                       \
            uint32_t a[4][4], b[2][4];                                         \
            _Pragma("unroll")                                                  \
            for (int mf = 0; mf < 4; mf++) {                                   \
                int row = warp_m * 64 + mf * 16 + a_row_off;                   \
                uint32_t g = (uint32_t)((ks * 2 + a_kh) ^ (row & 7));          \
                uint32_t addr = sA + (uint32_t)row * 128u + g * 16u;           \
                LDSM_X4(a[mf][0], a[mf][1], a[mf][2], a[mf][3], addr);         \
            }                                                                  \
            _Pragma("unroll")                                                  \
            for (int nf2 = 0; nf2 < 2; nf2++) {                                \
                int row = warp_n * 32 + nf2 * 16 + b_row_off;                  \
                uint32_t g = (uint32_t)((ks * 2 + b_kh) ^ (row & 7));          \
                uint32_t addr = sB + (uint32_t)row * 128u + g * 16u;           \
                LDSM_X4(b[nf2][0], b[nf2][1], b[nf2][2], b[nf2][3], addr);     \
            }                                                                  \
            _Pragma("unroll")                                                  \
            for (int mf = 0; mf < 4; mf++)                                     \
                _Pragma("unroll")                                              \
                for (int nf = 0; nf < 4; nf++) {                               \
                    uint32_t bb0 = b[nf >> 1][(nf & 1) * 2 + 0];               \
                    uint32_t bb1 = b[nf >> 1][(nf & 1) * 2 + 1];               \
                    MMA_TF32(acc[mf][nf], a[mf][0], a[mf][1], a[mf][2],        \
                             a[mf][3], bb0, bb1);                              \
                }                                                              \
        }                                                                      \
        if (++st >= NSTAGE) st = 0;                                            \
    }

// ---------------------------------------------------------------------------
// Generic GEMM NT (used for O projection): C = A * B^T
// ---------------------------------------------------------------------------
__global__ void __launch_bounds__(256) tmma_gemm_nt(const float* __restrict__ A,
                                                    const float* __restrict__ B,
                                                    float* __restrict__ C,
                                                    int N, int K) {
    extern __shared__ char smem[];
    const uint32_t sbase = smem_to_u32(smem);
    const int tid = threadIdx.x;
    const int lane = tid & 31;
    const int wid = tid >> 5;
    const int warp_m = wid & 1;
    const int warp_n = wid >> 1;
    const int row0 = blockIdx.x * TBM;
    const int col0 = blockIdx.y * TBN;

    const int seg = lane >> 3, r8 = lane & 7;
    const int a_row_off = ((seg & 1) << 3) + r8;
    const int a_kh = seg >> 1;
    const int b_row_off = ((seg >> 1) << 3) + r8;
    const int b_kh = seg & 1;

    float acc[4][4][4] = {};

    GEMM_MAINLOOP(A, B, K)

    #pragma unroll
    for (int mf = 0; mf < 4; mf++) {
        int grow = row0 + warp_m * 64 + mf * 16 + (lane >> 2);
        #pragma unroll
        for (int nf = 0; nf < 4; nf++) {
            int gcol = col0 + warp_n * 32 + nf * 8 + ((lane & 3) << 1);
            *(float2*)(C + (size_t)grow * N + gcol) =
                make_float2(acc[mf][nf][0], acc[mf][nf][1]);
            *(float2*)(C + (size_t)(grow + 8) * N + gcol) =
                make_float2(acc[mf][nf][2], acc[mf][nf][3]);
        }
    }
}

// ---------------------------------------------------------------------------
// QKV GEMM with FUSED RoPE + scale + bf16 hi/lo split epilogue (R15-proven).
// ---------------------------------------------------------------------------
__global__ void __launch_bounds__(256) tmma_gemm_qkv_fused(const float* __restrict__ A,
                                                           const float* __restrict__ B) {
    extern __shared__ char smem[];
    const uint32_t sbase = smem_to_u32(smem);
    const int tid = threadIdx.x;
    const int lane = tid & 31;
    const int wid = tid >> 5;
    const int warp_m = wid & 1;
    const int warp_n = wid >> 1;
    const int row0 = blockIdx.x * TBM;
    const int col0 = blockIdx.y * TBN;
    const int hh = blockIdx.y;           // head region (tile = one head)

    const int seg = lane >> 3, r8 = lane & 7;
    const int a_row_off = ((seg & 1) << 3) + r8;
    const int a_kh = seg >> 1;
    const int b_row_off = ((seg >> 1) << 3) + r8;
    const int b_kh = seg & 1;

    float acc[4][4][4] = {};

    GEMM_MAINLOOP(A, B, HIDDEN)

    // ---- epilogue: stage acc tile in smem (pipeline buffers are free) ----
    __syncthreads();
    float* T = (float*)smem;              // [128][EP_STRIDE]
    #pragma unroll
    for (int mf = 0; mf < 4; mf++) {
        int r = warp_m * 64 + mf * 16 + (lane >> 2);
        #pragma unroll
        for (int nf = 0; nf < 4; nf++) {
            int cc = warp_n * 32 + nf * 8 + ((lane & 3) << 1);
            *(float2*)(T + r * EP_STRIDE + cc) =
                make_float2(acc[mf][nf][0], acc[mf][nf][1]);
            *(float2*)(T + (r + 8) * EP_STRIDE + cc) =
                make_float2(acc[mf][nf][2], acc[mf][nf][3]);
        }
    }
    __syncthreads();

    __nv_bfloat16 *base_h, *base_l;
    int head;
    if (hh < 32)      { base_h = g_qh; base_l = g_ql; head = hh; }
    else if (hh < 40) { base_h = g_kh; base_l = g_kl; head = hh - 32; }
    else              { base_h = g_vh; base_l = g_vl; head = hh - 40; }
    const bool do_rope  = (hh < 40);
    const bool do_scale = (hh < 32);

    #pragma unroll 4
    for (int i = 0; i < 32; i++) {
        int e = tid + i * 256;            // 0..8191
        int r = e >> 6;                   // 0..127
        int d = e & 63;                   // 0..63
        float x1 = T[r * EP_STRIDE + d];
        float x2 = T[r * EP_STRIDE + d + 64];
        int s = row0 + r;

        float o1 = x1, o2 = x2;
        if (do_rope) {
            float freq = exp2f(-0.20762050593046013f * (float)d);
            float ang = (float)s * freq;
            float sn, cs;
            sincosf(ang, &sn, &cs);
            o1 = x1 * cs - x2 * sn;
            o2 = x1 * sn + x2 * cs;
        }
        if (do_scale) {
            const float scale = 0.08838834764831845f;   // 1/sqrt(128)
            o1 *= scale; o2 *= scale;
        }
        __nv_bfloat16 h1 = __float2bfloat16_rn(o1);
        __nv_bfloat16 h2 = __float2bfloat16_rn(o2);
        size_t off = ((size_t)head * S_LEN + s) * HD + d;
        base_h[off]      = h1;
        base_h[off + 64] = h2;
        base_l[off]      = __float2bfloat16_rn(o1 - __bfloat162float(h1));
        base_l[off + 64] = __float2bfloat16_rn(o2 - __bfloat162float(h2));
    }
}

// ===========================================================================
// Tensor-core flash attention, bf16 3-term compensated.
// 2 BARRIERS PER KV TILE (was 3). Per iteration kb:
//   top (kb>0): wait0 (K_kb done; only K outstanding), sync (== all warps
//               finished PV_{kb-1}), THEN commit V_kb loads (safe: V buffer
//               free, covered by QK+softmax).
//   mid: wait0 (V_kb done), sync (all warps done reading K_kb), commit
//        K_{kb+1} loads.
//   (no trailing sync — top sync of kb+1 provides the PV-done guarantee)
// Exactly one cp.async group outstanding at each wait; data-op order
// unchanged -> bit-identical numerics.
// ===========================================================================
#define ATT_SMEM (6 * 64 * 128 * 2)    // 98304 bytes
#define SQH 0
#define SQL 16384
#define SKH 32768
#define SKL 49152
#define SVH 65536
#define SVL 81920

__global__ void __launch_bounds__(128, 2) attn_mma() {
    extern __shared__ char smem[];
    const uint32_t sb = smem_to_u32(smem);
    const int tid = threadIdx.x;
    const int lane = tid & 31;
    const int wid = tid >> 5;
    const int mb = 31 - (int)blockIdx.x;     // heaviest first
    const int h = blockIdx.y;
    const int kvh = h >> 2;
    const int q0 = mb * 64;
    const int wr = wid * 16;
    const int gr = lane >> 2, tg = lane & 3;
    const int seg = lane >> 3, r8 = lane & 7;

    const __nv_bfloat16* qh = g_qh + ((size_t)h * S_LEN + q0) * HD;
    const __nv_bfloat16* ql = g_ql + ((size_t)h * S_LEN + q0) * HD;
    const __nv_bfloat16* kh = g_kh + (size_t)kvh * S_LEN * HD;
    const __nv_bfloat16* kl = g_kl + (size_t)kvh * S_LEN * HD;
    const __nv_bfloat16* vh = g_vh + (size_t)kvh * S_LEN * HD;
    const __nv_bfloat16* vl = g_vl + (size_t)kvh * S_LEN * HD;

    auto load_pair = [&](uint32_t dh, uint32_t dl,
                         const __nv_bfloat16* sh, const __nv_bfloat16* sl) {
        #pragma unroll
        for (int i = 0; i < 8; i++) {
            int e = tid + i * 128;
            int r = e >> 4, g = e & 15;
            uint32_t so = (uint32_t)r * 256u + (uint32_t)((g ^ (r & 7)) << 4);
            CP_ASYNC16(dh + so, sh + (size_t)r * HD + g * 8);
            CP_ASYNC16(dl + so, sl + (size_t)r * HD + g * 8);
        }
    };

    load_pair(sb + SQH, sb + SQL, qh, ql);
    load_pair(sb + SKH, sb + SKL, kh, kl);
    load_pair(sb + SVH, sb + SVL, vh, vl);
    CP_COMMIT();
    CP_WAIT0();
    __syncthreads();

    float oacc[16][4] = {};
    const float NEG_INF = -__int_as_float(0x7f800000);
    float m0 = NEG_INF, m1 = NEG_INF, l0 = 0.0f, l1 = 0.0f;

    const int a_row = wr + ((seg & 1) << 3) + r8;
    const int a_gsel = seg >> 1;
    const int b_row_off = ((seg >> 1) << 3) + r8;
    const int b_gsel = seg & 1;
    const int v_row_off = ((seg & 1) << 3) + r8;
    const int v_gsel = seg >> 1;

    for (int kb = 0; kb <= mb; kb++) {
        if (kb > 0) {
            CP_WAIT0();                   // K_kb resident (only K outstanding)
            __syncthreads();              // also: all warps finished PV_{kb-1}
            // V buffer now free -> prefetch V_kb (covered by QK+softmax)
            load_pair(sb + SVH, sb + SVL,
                      vh + (size_t)kb * 64 * HD,
                      vl + (size_t)kb * 64 * HD);
            CP_COMMIT();
        }

        // ---------------- S = Q K^T (bf16 x3) ----------------
        float sacc[8][4] = {};
        #pragma unroll
        for (int kc = 0; kc < 8; kc++) {
            uint32_t qa_h[4], qa_l[4];
            {
                uint32_t g = (uint32_t)((2 * kc + a_gsel) ^ (a_row & 7));
                uint32_t off = (uint32_t)a_row * 256u + g * 16u;
                LDSM_X4(qa_h[0], qa_h[1], qa_h[2], qa_h[3], sb + SQH + off);
                LDSM_X4(qa_l[0], qa_l[1], qa_l[2], qa_l[3], sb + SQL + off);
            }
            #pragma unroll
            for (int nf2 = 0; nf2 < 4; nf2++) {
                int brow = nf2 * 16 + b_row_off;
                uint32_t g = (uint32_t)((2 * kc + b_gsel) ^ (brow & 7));
                uint32_t off = (uint32_t)brow * 256u + g * 16u;
                uint32_t bh0, bh1, bh2, bh3, bl0, bl1, bl2, bl3;
                LDSM_X4(bh0, bh1, bh2, bh3, sb + SKH + off);
                LDSM_X4(bl0, bl1, bl2, bl3, sb + SKL + off);
                MMA_BF16(sacc[2 * nf2],     qa_h, bh0, bh1);
                MMA_BF16(sacc[2 * nf2],     qa_l, bh0, bh1);
                MMA_BF16(sacc[2 * nf2],     qa_h, bl0, bl1);
                MMA_BF16(sacc[2 * nf2 + 1], qa_h, bh2, bh3);
                MMA_BF16(sacc[2 * nf2 + 1], qa_l, bh2, bh3);
                MMA_BF16(sacc[2 * nf2 + 1], qa_h, bl2, bl3);
            }
        }

        // ---------------- online softmax (registers only) ----------------
        const int row0g = q0 + wr + gr;
        const int row1g = row0g + 8;
        if (kb == mb) {
            const int n0 = kb * 64;
            #pragma unroll
            for (int nf = 0; nf < 8; nf++) {
                int c0 = n0 + nf * 8 + 2 * tg;
                if (c0 > row0g)     sacc[nf][0] = NEG_INF;
                if (c0 + 1 > row0g) sacc[nf][1] = NEG_INF;
                if (c0 > row1g)     sacc[nf][2] = NEG_INF;
                if (c0 + 1 > row1g) sacc[nf][3] = NEG_INF;
            }
        }
        float mx0 = NEG_INF, mx1 = NEG_INF;
        #pragma unroll
        for (int nf = 0; nf < 8; nf++) {
            mx0 = fmaxf(mx0, fmaxf(sacc[nf][0], sacc[nf][1]));
            mx1 = fmaxf(mx1, fmaxf(sacc[nf][2], sacc[nf][3]));
        }
        mx0 = fmaxf(mx0, __shfl_xor_sync(0xffffffffu, mx0, 1));
        mx0 = fmaxf(mx0, __shfl_xor_sync(0xffffffffu, mx0, 2));
        mx1 = fmaxf(mx1, __shfl_xor_sync(0xffffffffu, mx1, 1));
        mx1 = fmaxf(mx1, __shfl_xor_sync(0xffffffffu, mx1, 2));
        float mn0 = fmaxf(m0, mx0), mn1 = fmaxf(m1, mx1);
        float rs0 = __expf(m0 - mn0), rs1 = __expf(m1 - mn1);
        float sum0 = 0.0f, sum1 = 0.0f;
        #pragma unroll
        for (int nf = 0; nf < 8; nf++) {
            sacc[nf][0] = __expf(sacc[nf][0] - mn0); sum0 += sacc[nf][0];
            sacc[nf][1] = __expf(sacc[nf][1] - mn0); sum0 += sacc[nf][1];
            sacc[nf][2] = __expf(sacc[nf][2] - mn1); sum1 += sacc[nf][2];
            sacc[nf][3] = __expf(sacc[nf][3] - mn1); sum1 += sacc[nf][3];
        }
        sum0 += __shfl_xor_sync(0xffffffffu, sum0, 1);
        sum0 += __shfl_xor_sync(0xffffffffu, sum0, 2);
        sum1 += __shfl_xor_sync(0xffffffffu, sum1, 1);
        sum1 += __shfl_xor_sync(0xffffffffu, sum1, 2);
        l0 = l0 * rs0 + sum0; m0 = mn0;
        l1 = l1 * rs1 + sum1; m1 = mn1;
        #pragma unroll
        for (int nf = 0; nf < 16; nf++) {
            oacc[nf][0] *= rs0; oacc[nf][1] *= rs0;
            oacc[nf][2] *= rs1; oacc[nf][3] *= rs1;
        }

        // V_kb resident + all warps done reading K_kb -> K prefetch is safe
        CP_WAIT0();
        __syncthreads();
        if (kb < mb) {                    // prefetch next K into freed K buffer
            load_pair(sb + SKH, sb + SKL,
                      kh + (size_t)(kb + 1) * 64 * HD,
                      kl + (size_t)(kb + 1) * 64 * HD);
            CP_COMMIT();
        }

        // ---------------- O += P V (bf16 x3, P from regs) ----------------
        #pragma unroll
        for (int kc2 = 0; kc2 < 4; kc2++) {
            uint32_t pa_h[4], pa_l[4];
            pa_h[0] = pack_bf16_hi(sacc[2 * kc2][0],     sacc[2 * kc2][1]);
            pa_h[1] = pack_bf16_hi(sacc[2 * kc2][2],     sacc[2 * kc2][3]);
            pa_h[2] = pack_bf16_hi(sacc[2 * kc2 + 1][0], sacc[2 * kc2 + 1][1]);
            pa_h[3] = pack_bf16_hi(sacc[2 * kc2 + 1][2], sacc[2 * kc2 + 1][3]);
            pa_l[0] = pack_bf16_lo(sacc[2 * kc2][0],     sacc[2 * kc2][1],     pa_h[0]);
            pa_l[1] = pack_bf16_lo(sacc[2 * kc2][2],     sacc[2 * kc2][3],     pa_h[1]);
            pa_l[2] = pack_bf16_lo(sacc[2 * kc2 + 1][0], sacc[2 * kc2 + 1][1], pa_h[2]);
            pa_l[3] = pack_bf16_lo(sacc[2 * kc2 + 1][2], sacc[2 * kc2 + 1][3], pa_h[3]);
            int krow = 16 * kc2 + v_row_off;
            #pragma unroll
            for (int j = 0; j < 8; j++) {
                uint32_t g = (uint32_t)((2 * j + v_gsel) ^ (krow & 7));
                uint32_t off = (uint32_t)krow * 256u + g * 16u;
                uint32_t vh0, vh1, vh2, vh3, vl0, vl1, vl2, vl3;
                LDSM_X4_T(vh0, vh1, vh2, vh3, sb + SVH + off);
                LDSM_X4_T(vl0, vl1, vl2, vl3, sb + SVL + off);
                MMA_BF16(oacc[2 * j],     pa_h, vh0, vh1);
                MMA_BF16(oacc[2 * j],     pa_l, vh0, vh1);
                MMA_BF16(oacc[2 * j],     pa_h, vl0, vl1);
                MMA_BF16(oacc[2 * j + 1], pa_h, vh2, vh3);
                MMA_BF16(oacc[2 * j + 1], pa_l, vh2, vh3);
                MMA_BF16(oacc[2 * j + 1], pa_h, vl2, vl3);
            }
        }
        // no trailing sync: top sync of kb+1 guarantees PV-done before V STS
    }

    // ---------------- normalize + tf32-round + writeout ----------------
    const float inv0 = 1.0f / l0, inv1 = 1.0f / l1;
    const int row0g = q0 + wr + gr;
    float* dst0 = g_attn + (size_t)row0g * (NH * HD) + h * HD;
    float* dst1 = dst0 + 8 * (size_t)(NH * HD);
    #pragma unroll
    for (int nf = 0; nf < 16; nf++) {
        int col = nf * 8 + 2 * tg;
        *(float2*)(dst0 + col) = make_float2(round_tf32f(oacc[nf][0] * inv0),
                                             round_tf32f(oacc[nf][1] * inv0));
        *(float2*)(dst1 + col) = make_float2(round_tf32f(oacc[nf][2] * inv1),
                                             round_tf32f(oacc[nf][3] * inv1));
    }
}

// ---------------------------------------------------------------------------
extern "C" void kernel_launch(void* const* d_in, const int* in_sizes, int n_in,
                              void* d_out, int out_size) {
    const float* hidden = (const float*)d_in[0];
    const float* w_qkv  = (const float*)d_in[1];
    const float* w_o    = (const float*)d_in[2];
    float* out = (float*)d_out;

    float *attn = nullptr;
    float *hid_r = nullptr, *wqkv_r = nullptr, *wo_r = nullptr;
    cudaGetSymbolAddress((void**)&attn,   g_attn);
    cudaGetSymbolAddress((void**)&hid_r,  g_hid_r);
    cudaGetSymbolAddress((void**)&wqkv_r, g_wqkv_r);
    cudaGetSymbolAddress((void**)&wo_r,   g_wo_r);

    cudaFuncSetAttribute(tmma_gemm_nt, cudaFuncAttributeMaxDynamicSharedMemorySize,
                         GEMM_SMEM_TOTAL);
    cudaFuncSetAttribute(tmma_gemm_qkv_fused,
                         cudaFuncAttributeMaxDynamicSharedMemorySize,
                         GEMM_SMEM_TOTAL);
    cudaFuncSetAttribute(attn_mma, cudaFuncAttributeMaxDynamicSharedMemorySize,
                         ATT_SMEM);

    // 0) merged tf32 pre-rounding of all GEMM operands (single launch)
    {
        const int n1 = (QKV_DIM * HIDDEN) / 4;
        const int n2 = (HIDDEN * NH * HD) / 4;
        const int n3 = (S_LEN * HIDDEN) / 4;
        const int nt = n1 + n2 + n3;
        round3_tf32_kernel<<<(nt + 255) / 256, 256>>>(w_qkv, wqkv_r, n1,
                                                      w_o, wo_r, n2,
                                                      hidden, hid_r, n3);
    }

    // 1) QKV projection + fused RoPE/scale/bf16-split -> head-major Q/K/V
    tmma_gemm_qkv_fused<<<dim3(S_LEN / TBM, QKV_DIM / TBN), 256, GEMM_SMEM_TOTAL>>>(
        hid_r, wqkv_r);

    // 2) Causal GQA flash attention (bf16 x3 tensor core) -> g_attn (tf32-rounded)
    attn_mma<<<dim3(32, NH), 128, ATT_SMEM>>>();

    // 3) Output projection (tf32 mma): out = g_attn @ w_o^T
    tmma_gemm_nt<<<dim3(S_LEN / TBM, HIDDEN / TBN), 256, GEMM_SMEM_TOTAL>>>(
        attn, wo_r, out, HIDDEN, HIDDEN);
}